// round 13
// baseline (speedup 1.0000x reference)
#include <cuda_runtime.h>
#include <cuda_fp16.h>
#include <math.h>

// Problem constants: B=256, T=200, X=128, H=512, NU=100, cin=1152.
#define NB 256
#define NT 200
#define NX 128
#define NH 512
#define NTH 1024

// Device-global scratch (allocation-free).
__device__ float g_xpu[NT * NB * 100];
__device__ float g_xpr[NT * NB * 100];
__device__ float g_xpn[NT * NB * 100];

// fp16 weight streams.
// Phase-1 pack: uint4 at (k2, g) = 4 cols x half2(k-pair):
//   idx = (k2*25 + (j>>2))*8 + (j&3)*2 + (k&1)
__device__ __half g_hWo1[512  * 100];
__device__ __half g_hWu1[1024 * 100];
__device__ __half g_hWr1[1024 * 100];
__device__ __half g_hWn1[1024 * 100];
// Phase-2 pack: half2 per (j2, col): idx = ((j>>1)*ncol + c)*2 + (j&1)
__device__ __half g_hWo2[100 * 512];
__device__ __half g_hWu2[100 * 512];
__device__ __half g_hWr2[100 * 512];
__device__ __half g_hWn2[100 * 1024];

// ---------------------------------------------------------------------------
__global__ void pack_p1_kernel(const float* __restrict__ src, __half* __restrict__ dst, int nrows) {
    int n = nrows * 100;
    for (int i = blockIdx.x * blockDim.x + threadIdx.x; i < n; i += gridDim.x * blockDim.x) {
        int k = i / 100, j = i % 100;
        dst[((k >> 1) * 25 + (j >> 2)) * 8 + (j & 3) * 2 + (k & 1)] = __float2half_rn(src[i]);
    }
}

__global__ void pack_p2_kernel(const float* __restrict__ src, __half* __restrict__ dst, int ncol) {
    int n = 100 * ncol;
    for (int i = blockIdx.x * blockDim.x + threadIdx.x; i < n; i += gridDim.x * blockDim.x) {
        int j = i / ncol, c = i % ncol;
        dst[(((j >> 1) * ncol) + c) * 2 + (j & 1)] = __float2half_rn(src[i]);
    }
}

// ---------------------------------------------------------------------------
// Prep: g_xp*[t][b][j] = b*1[j] + sum_i x[b][t][i] * W*1[(1024+i)*100 + j]  (fp32)
// ---------------------------------------------------------------------------
__global__ __launch_bounds__(256) void prep_xproj_kernel(
    const float* __restrict__ x,
    const float* __restrict__ Wu1, const float* __restrict__ bu1,
    const float* __restrict__ Wr1, const float* __restrict__ br1,
    const float* __restrict__ Wn1, const float* __restrict__ bn1)
{
    int t   = blockIdx.x;
    int bt  = blockIdx.y;
    int tid = threadIdx.x;
    if (tid >= 200) return;
    int j  = tid % 100;
    int s  = tid / 100;
    int b0 = bt * 16 + s * 8;

    float au[8], ar[8], an[8];
    float vbu = bu1[j], vbr = br1[j], vbn = bn1[j];
#pragma unroll
    for (int bi = 0; bi < 8; bi++) { au[bi] = vbu; ar[bi] = vbr; an[bi] = vbn; }

    for (int i = 0; i < NX; i += 4) {
        float wu[4], wr[4], wn[4];
#pragma unroll
        for (int c = 0; c < 4; c++) {
            int wi = (2 * NH + i + c) * 100 + j;
            wu[c] = __ldg(Wu1 + wi);
            wr[c] = __ldg(Wr1 + wi);
            wn[c] = __ldg(Wn1 + wi);
        }
#pragma unroll
        for (int bi = 0; bi < 8; bi++) {
            float4 xv = *reinterpret_cast<const float4*>(
                x + ((size_t)(b0 + bi) * NT + t) * NX + i);
            au[bi] += xv.x * wu[0] + xv.y * wu[1] + xv.z * wu[2] + xv.w * wu[3];
            ar[bi] += xv.x * wr[0] + xv.y * wr[1] + xv.z * wr[2] + xv.w * wr[3];
            an[bi] += xv.x * wn[0] + xv.y * wn[1] + xv.z * wn[2] + xv.w * wn[3];
        }
    }
#pragma unroll
    for (int bi = 0; bi < 8; bi++) {
        int idx = (t * NB + b0 + bi) * 100 + j;
        g_xpu[idx] = au[bi];
        g_xpr[idx] = ar[bi];
        g_xpn[idx] = an[bi];
    }
}

__device__ __forceinline__ float fast_tanh(float x) {
    float y;
    asm("tanh.approx.f32 %0, %1;" : "=f"(y) : "f"(x));
    return y;
}
__device__ __forceinline__ float sigm(float v) {
    return 0.5f * fast_tanh(0.5f * v) + 0.5f;
}
__device__ __forceinline__ void promote(float& af, __half2& ah) {
    float2 f = __half22float2(ah);
    af += f.x + f.y;
    ah = __float2half2_rn(0.f);
}

// ---------------------------------------------------------------------------
// Persistent recurrent kernel: 128 blocks x 1024 threads.
// HFMA2 inner products (fp16 weights+activations), fp32 state & blending.
// ---------------------------------------------------------------------------
__global__ __launch_bounds__(NTH) void odegru_kernel(
    const float* __restrict__ xt,
    const float* __restrict__ Wt1, const float* __restrict__ bt1,
    const float* __restrict__ Wt2, const float* __restrict__ bt2,
    const float* __restrict__ Wt3, const float* __restrict__ bt3,
    const float* __restrict__ bo1, const float* __restrict__ bo2,
    const float* __restrict__ bu2, const float* __restrict__ br2,
    const float* __restrict__ bn2,
    float* __restrict__ out)
{
    // fp32 state
    __shared__ __align__(16) float sh_h [2][NH];
    __shared__ __align__(16) float sh_hs[2][NH];
    __shared__ __align__(16) float sh_ho[2][NH];
    __shared__ __align__(16) float sh_u [2][NH];
    __shared__ __align__(16) float sh_t1[2][100];   // head only
    __shared__ __align__(16) float sh_t2[2][100];   // head only
    __shared__ __align__(16) float sh_part[32 * 2 * 100];
    __shared__ float sh_dt[NT];
    // fp16 shadows for HFMA2 consumption
    __shared__ __align__(8) __half sh16_h [2][NH];
    __shared__ __align__(8) __half sh16_hs[2][NH];
    __shared__ __align__(8) __half sh16_ho[2][NH];
    __shared__ __align__(8) __half sh16_ch[2][NH];
    __shared__ __align__(8) __half sh16_cs[2][NH];
    __shared__ __align__(8) __half sh16_t1[50][2][2];   // [j2][row][e]
    __shared__ __align__(8) __half sh16_t2[50][2][2];

    const int tid = threadIdx.x;
    const int b0  = blockIdx.x * 2;
    const __half2 hz = __float2half2_rn(0.f);

    // phase-1 mappings
    const int g25 = tid % 25;
    const int c32 = tid / 25;           // 0..31 (tid<800)
    const int gateB = tid / 400;        // B1: 0=u, 1=r
    const int sB    = tid % 400;
    const int cB    = sB / 25;          // 0..15
    const int gB    = sB % 25;
    // reduce mappings
    const int rrow  = (tid / 100) & 1, rj = tid % 100;
    const int rgate = tid / 200;
    // phase-2 column mappings
    const int gcol  = tid >> 9;
    const int col   = tid & 511;

    if (tid < NT) {
        float v;
        if (tid == 0)      v = -0.01f;
        else if (tid == 1) v = xt[NT - 1] - xt[0];
        else               v = xt[tid - 2] - xt[tid - 1];
        sh_dt[tid] = v;
    }
    for (int k = tid; k < NH; k += NTH) {
        sh_h[0][k] = 0.f; sh_h[1][k] = 0.f;
        sh_hs[0][k] = 0.f; sh_hs[1][k] = 0.f;
        __half z = __float2half_rn(0.f);
        sh16_h[0][k] = z; sh16_h[1][k] = z;
        sh16_hs[0][k] = z; sh16_hs[1][k] = z;
    }
    __syncthreads();

    for (int t = 0; t < NT; t++) {
        const float dt = sh_dt[t];

        // Prefetch this step's x-projection values.
        float pf_ur = 0.f, pf_n = 0.f;
        if (tid < 400) {
            int idx = (t * NB + b0 + rrow) * 100 + rj;
            pf_ur = rgate ? __ldg(g_xpr + idx) : __ldg(g_xpu + idx);
            if (tid < 200) pf_n = __ldg(g_xpn + idx);
        }

        // ---- Phase A1: a = tanh(h @ Wo1 + bo1); 32 chunks x 8 k2 ----
        if (tid < 800) {
            float4 a0f = {0.f,0.f,0.f,0.f}, a1f = {0.f,0.f,0.f,0.f};
            __half2 a00=hz,a01=hz,a02=hz,a03=hz,a10=hz,a11=hz,a12=hz,a13=hz;
            const __half* wp = g_hWo1 + ((size_t)(c32 * 8) * 25 + g25) * 8;
            const __half2* sp0 = reinterpret_cast<const __half2*>(&sh16_h[0][0]) + c32 * 8;
            const __half2* sp1 = reinterpret_cast<const __half2*>(&sh16_h[1][0]) + c32 * 8;
#pragma unroll
            for (int k2 = 0; k2 < 8; k2++) {
                uint4 q = *reinterpret_cast<const uint4*>(wp); wp += 200;
                const __half2* hw = reinterpret_cast<const __half2*>(&q);
                __half2 v0 = sp0[k2], v1 = sp1[k2];
                a00 = __hfma2(v0, hw[0], a00); a01 = __hfma2(v0, hw[1], a01);
                a02 = __hfma2(v0, hw[2], a02); a03 = __hfma2(v0, hw[3], a03);
                a10 = __hfma2(v1, hw[0], a10); a11 = __hfma2(v1, hw[1], a11);
                a12 = __hfma2(v1, hw[2], a12); a13 = __hfma2(v1, hw[3], a13);
            }
            promote(a0f.x, a00); promote(a0f.y, a01); promote(a0f.z, a02); promote(a0f.w, a03);
            promote(a1f.x, a10); promote(a1f.y, a11); promote(a1f.z, a12); promote(a1f.w, a13);
            *reinterpret_cast<float4*>(&sh_part[(c32 * 2 + 0) * 100 + 4 * g25]) = a0f;
            *reinterpret_cast<float4*>(&sh_part[(c32 * 2 + 1) * 100 + 4 * g25]) = a1f;
        }
        __syncthreads();
        if (tid < 200) {
            float s = bo1[rj];
#pragma unroll
            for (int cc = 0; cc < 32; cc++) s += sh_part[(cc * 2 + rrow) * 100 + rj];
            float v = fast_tanh(s);
            sh16_t1[rj >> 1][rrow][rj & 1] = __float2half_rn(v);
        }
        __syncthreads();

        // ---- Phase A2: h_ode = h + dt*(a @ Wo2 + bo2); 512 cols, both rows ----
        if (tid < 512) {
            float f0 = bo2[col], f1 = f0;
            __half2 a0 = hz, a1 = hz;
            const __half2* wp = reinterpret_cast<const __half2*>(g_hWo2) + col;
            const uint2* tp = reinterpret_cast<const uint2*>(&sh16_t1[0][0][0]);
#pragma unroll
            for (int run = 0; run < 5; run++) {
#pragma unroll
                for (int jj = 0; jj < 10; jj++) {
                    uint2 tt = tp[run * 10 + jj];
                    __half2 t0 = *reinterpret_cast<__half2*>(&tt.x);
                    __half2 t1 = *reinterpret_cast<__half2*>(&tt.y);
                    __half2 w = *wp; wp += NH;
                    a0 = __hfma2(t0, w, a0);
                    a1 = __hfma2(t1, w, a1);
                }
                promote(f0, a0); promote(f1, a1);
            }
            float ho0 = sh_h[0][col] + dt * f0;
            float ho1 = sh_h[1][col] + dt * f1;
            sh_ho[0][col] = ho0; sh_ho[1][col] = ho1;
            sh16_ho[0][col] = __float2half_rn(ho0);
            sh16_ho[1][col] = __float2half_rn(ho1);
        }
        __syncthreads();

        // ---- Phase B1: tu/tr = tanh(xp + [ho,hs] @ W{u,r}1); 16 chunks x 32 k2 ----
        if (tid < 800) {
            float4 a0f = {0.f,0.f,0.f,0.f}, a1f = {0.f,0.f,0.f,0.f};
            const __half* wp = (gateB ? g_hWr1 : g_hWu1) + ((size_t)(cB * 32) * 25 + gB) * 8;
            const __half2 *sp0, *sp1;
            if (cB < 8) {
                sp0 = reinterpret_cast<const __half2*>(&sh16_ho[0][0]) + cB * 32;
                sp1 = reinterpret_cast<const __half2*>(&sh16_ho[1][0]) + cB * 32;
            } else {
                sp0 = reinterpret_cast<const __half2*>(&sh16_hs[0][0]) + (cB - 8) * 32;
                sp1 = reinterpret_cast<const __half2*>(&sh16_hs[1][0]) + (cB - 8) * 32;
            }
#pragma unroll
            for (int run = 0; run < 2; run++) {
                __half2 a00=hz,a01=hz,a02=hz,a03=hz,a10=hz,a11=hz,a12=hz,a13=hz;
#pragma unroll
                for (int kk = 0; kk < 16; kk++) {
                    int k2 = run * 16 + kk;
                    uint4 q = *reinterpret_cast<const uint4*>(wp); wp += 200;
                    const __half2* hw = reinterpret_cast<const __half2*>(&q);
                    __half2 v0 = sp0[k2], v1 = sp1[k2];
                    a00 = __hfma2(v0, hw[0], a00); a01 = __hfma2(v0, hw[1], a01);
                    a02 = __hfma2(v0, hw[2], a02); a03 = __hfma2(v0, hw[3], a03);
                    a10 = __hfma2(v1, hw[0], a10); a11 = __hfma2(v1, hw[1], a11);
                    a12 = __hfma2(v1, hw[2], a12); a13 = __hfma2(v1, hw[3], a13);
                }
                promote(a0f.x, a00); promote(a0f.y, a01); promote(a0f.z, a02); promote(a0f.w, a03);
                promote(a1f.x, a10); promote(a1f.y, a11); promote(a1f.z, a12); promote(a1f.w, a13);
            }
            *reinterpret_cast<float4*>(&sh_part[(cB * 4 + gateB * 2 + 0) * 100 + 4 * gB]) = a0f;
            *reinterpret_cast<float4*>(&sh_part[(cB * 4 + gateB * 2 + 1) * 100 + 4 * gB]) = a1f;
        }
        __syncthreads();
        if (tid < 400) {
            if (rgate == 0) {
                float su = pf_ur;
#pragma unroll
                for (int cc = 0; cc < 16; cc++) su += sh_part[(cc * 4 + rrow) * 100 + rj];
                sh16_t1[rj >> 1][rrow][rj & 1] = __float2half_rn(fast_tanh(su));
            } else {
                float sr = pf_ur;
#pragma unroll
                for (int cc = 0; cc < 16; cc++) sr += sh_part[(cc * 4 + 2 + rrow) * 100 + rj];
                sh16_t2[rj >> 1][rrow][rj & 1] = __float2half_rn(fast_tanh(sr));
            }
        }
        __syncthreads();

        // ---- Phase B2: u/r per column, both rows ----
        {
            const __half2* wp = (gcol ? reinterpret_cast<const __half2*>(g_hWr2)
                                      : reinterpret_cast<const __half2*>(g_hWu2)) + col;
            const uint2* tp = gcol ? reinterpret_cast<const uint2*>(&sh16_t2[0][0][0])
                                   : reinterpret_cast<const uint2*>(&sh16_t1[0][0][0]);
            float f0 = gcol ? br2[col] : bu2[col];
            float f1 = f0;
            __half2 a0 = hz, a1 = hz;
#pragma unroll
            for (int run = 0; run < 5; run++) {
#pragma unroll
                for (int jj = 0; jj < 10; jj++) {
                    uint2 tt = tp[run * 10 + jj];
                    __half2 t0 = *reinterpret_cast<__half2*>(&tt.x);
                    __half2 t1 = *reinterpret_cast<__half2*>(&tt.y);
                    __half2 w = *wp; wp += NH;
                    a0 = __hfma2(t0, w, a0);
                    a1 = __hfma2(t1, w, a1);
                }
                promote(f0, a0); promote(f1, a1);
            }
            if (gcol == 0) {
                sh_u[0][col] = sigm(f0);
                sh_u[1][col] = sigm(f1);
            } else {
                float r0 = sigm(f0), r1 = sigm(f1);
                float ch0 = sh_ho[0][col] * r0, ch1 = sh_ho[1][col] * r1;
                float cs0 = sh_hs[0][col] * r0, cs1 = sh_hs[1][col] * r1;
                sh16_ch[0][col] = __float2half_rn(ch0);
                sh16_ch[1][col] = __float2half_rn(ch1);
                sh16_cs[0][col] = __float2half_rn(cs0);
                sh16_cs[1][col] = __float2half_rn(cs1);
            }
        }
        __syncthreads();

        // ---- Phase C1: tn = tanh(xpn + [ch,cs] @ Wn1); 32 chunks x 16 k2 ----
        if (tid < 800) {
            float4 a0f = {0.f,0.f,0.f,0.f}, a1f = {0.f,0.f,0.f,0.f};
            __half2 a00=hz,a01=hz,a02=hz,a03=hz,a10=hz,a11=hz,a12=hz,a13=hz;
            const __half* wp = g_hWn1 + ((size_t)(c32 * 16) * 25 + g25) * 8;
            const __half2 *sp0, *sp1;
            if (c32 < 16) {
                sp0 = reinterpret_cast<const __half2*>(&sh16_ch[0][0]) + c32 * 16;
                sp1 = reinterpret_cast<const __half2*>(&sh16_ch[1][0]) + c32 * 16;
            } else {
                sp0 = reinterpret_cast<const __half2*>(&sh16_cs[0][0]) + (c32 - 16) * 16;
                sp1 = reinterpret_cast<const __half2*>(&sh16_cs[1][0]) + (c32 - 16) * 16;
            }
#pragma unroll
            for (int k2 = 0; k2 < 16; k2++) {
                uint4 q = *reinterpret_cast<const uint4*>(wp); wp += 200;
                const __half2* hw = reinterpret_cast<const __half2*>(&q);
                __half2 v0 = sp0[k2], v1 = sp1[k2];
                a00 = __hfma2(v0, hw[0], a00); a01 = __hfma2(v0, hw[1], a01);
                a02 = __hfma2(v0, hw[2], a02); a03 = __hfma2(v0, hw[3], a03);
                a10 = __hfma2(v1, hw[0], a10); a11 = __hfma2(v1, hw[1], a11);
                a12 = __hfma2(v1, hw[2], a12); a13 = __hfma2(v1, hw[3], a13);
            }
            promote(a0f.x, a00); promote(a0f.y, a01); promote(a0f.z, a02); promote(a0f.w, a03);
            promote(a1f.x, a10); promote(a1f.y, a11); promote(a1f.z, a12); promote(a1f.w, a13);
            *reinterpret_cast<float4*>(&sh_part[(c32 * 2 + 0) * 100 + 4 * g25]) = a0f;
            *reinterpret_cast<float4*>(&sh_part[(c32 * 2 + 1) * 100 + 4 * g25]) = a1f;
        }
        __syncthreads();
        if (tid < 200) {
            float sn = pf_n;
#pragma unroll
            for (int cc = 0; cc < 32; cc++) sn += sh_part[(cc * 2 + rrow) * 100 + rj];
            sh16_t1[rj >> 1][rrow][rj & 1] = __float2half_rn(fast_tanh(sn));
        }
        __syncthreads();

        // ---- Phase C2: ns = tn @ Wn2 + bn2; m/s per column; state update ----
        {
            const __half2* wp = reinterpret_cast<const __half2*>(g_hWn2) + gcol * NH + col;
            const uint2* tp = reinterpret_cast<const uint2*>(&sh16_t1[0][0][0]);
            float f0 = bn2[gcol * NH + col], f1 = f0;
            __half2 a0 = hz, a1 = hz;
#pragma unroll
            for (int run = 0; run < 5; run++) {
#pragma unroll
                for (int jj = 0; jj < 10; jj++) {
                    uint2 tt = tp[run * 10 + jj];
                    __half2 t0 = *reinterpret_cast<__half2*>(&tt.x);
                    __half2 t1 = *reinterpret_cast<__half2*>(&tt.y);
                    __half2 w = *wp; wp += 2 * NH;
                    a0 = __hfma2(t0, w, a0);
                    a1 = __hfma2(t1, w, a1);
                }
                promote(f0, a0); promote(f1, a1);
            }
            float u0 = sh_u[0][col], u1 = sh_u[1][col];
            if (gcol == 0) {
                float h0 = (1.f - u0) * f0 + u0 * sh_ho[0][col];
                float h1 = (1.f - u1) * f1 + u1 * sh_ho[1][col];
                sh_h[0][col] = h0; sh_h[1][col] = h1;
                sh16_h[0][col] = __float2half_rn(h0);
                sh16_h[1][col] = __float2half_rn(h1);
            } else {
                float s0 = (1.f - u0) * fabsf(f0) + u0 * sh_hs[0][col];
                float s1 = (1.f - u1) * fabsf(f1) + u1 * sh_hs[1][col];
                sh_hs[0][col] = s0; sh_hs[1][col] = s1;
                sh16_hs[0][col] = __float2half_rn(s0);
                sh16_hs[1][col] = __float2half_rn(s1);
            }
        }
        __syncthreads();
    }

    // ================= Final head (fp32, run once) =================
    if (tid < 800) {
        float4 a0 = {0.f,0.f,0.f,0.f}, a1 = {0.f,0.f,0.f,0.f};
        const int kk0 = c32 * 32;
        const float* wp = Wt1 + kk0 * 100 + 4 * g25;
        const float *sp0, *sp1;
        if (kk0 < NH) { sp0 = &sh_h[0][kk0];       sp1 = &sh_h[1][kk0]; }
        else          { sp0 = &sh_hs[0][kk0 - NH]; sp1 = &sh_hs[1][kk0 - NH]; }
#pragma unroll 8
        for (int kc = 0; kc < 32; kc++) {
            float4 w = *reinterpret_cast<const float4*>(wp); wp += 100;
            float v0 = sp0[kc], v1 = sp1[kc];
            a0.x += v0 * w.x; a0.y += v0 * w.y; a0.z += v0 * w.z; a0.w += v0 * w.w;
            a1.x += v1 * w.x; a1.y += v1 * w.y; a1.z += v1 * w.z; a1.w += v1 * w.w;
        }
        *reinterpret_cast<float4*>(&sh_part[(c32 * 2 + 0) * 100 + 4 * g25]) = a0;
        *reinterpret_cast<float4*>(&sh_part[(c32 * 2 + 1) * 100 + 4 * g25]) = a1;
    }
    __syncthreads();
    if (tid < 200) {
        float s = bt1[rj];
#pragma unroll
        for (int cc = 0; cc < 32; cc++) s += sh_part[(cc * 2 + rrow) * 100 + rj];
        sh_t1[rrow][rj] = tanhf(s);
    }
    __syncthreads();
    if (tid < 200) {
        float s = bt2[rj];
#pragma unroll 4
        for (int jj = 0; jj < 100; jj++) s += sh_t1[rrow][jj] * Wt2[jj * 100 + rj];
        sh_t2[rrow][rj] = tanhf(s);
    }
    __syncthreads();
    {
        float b = bt3[tid];
        float a0 = b, a1 = b;
        const float* wp = Wt3 + tid;
#pragma unroll 10
        for (int j = 0; j < 100; j++) {
            float w = *wp; wp += 2 * NH;
            a0 += sh_t2[0][j] * w;
            a1 += sh_t2[1][j] * w;
        }
        if (gcol == 0) {
            out[(size_t)(b0 + 0) * NH + col] = a0;
            out[(size_t)(b0 + 1) * NH + col] = a1;
        } else {
            out[(size_t)NB * NH + (size_t)(b0 + 0) * NH + col] = fabsf(a0);
            out[(size_t)NB * NH + (size_t)(b0 + 1) * NH + col] = fabsf(a1);
        }
    }
}

// ---------------------------------------------------------------------------
extern "C" void kernel_launch(void* const* d_in, const int* in_sizes, int n_in,
                              void* d_out, int out_size) {
    const float* x   = (const float*)d_in[0];
    const float* xt  = (const float*)d_in[1];
    const float* Wu1 = (const float*)d_in[2];
    const float* bu1 = (const float*)d_in[3];
    const float* Wu2 = (const float*)d_in[4];
    const float* bu2 = (const float*)d_in[5];
    const float* Wr1 = (const float*)d_in[6];
    const float* br1 = (const float*)d_in[7];
    const float* Wr2 = (const float*)d_in[8];
    const float* br2 = (const float*)d_in[9];
    const float* Wn1 = (const float*)d_in[10];
    const float* bn1 = (const float*)d_in[11];
    const float* Wn2 = (const float*)d_in[12];
    const float* bn2 = (const float*)d_in[13];
    const float* Wo1 = (const float*)d_in[14];
    const float* bo1 = (const float*)d_in[15];
    const float* Wo2 = (const float*)d_in[16];
    const float* bo2 = (const float*)d_in[17];
    const float* Wt1 = (const float*)d_in[18];
    const float* bt1 = (const float*)d_in[19];
    const float* Wt2 = (const float*)d_in[20];
    const float* bt2 = (const float*)d_in[21];
    const float* Wt3 = (const float*)d_in[22];
    const float* bt3 = (const float*)d_in[23];
    float* out = (float*)d_out;

    __half *hWo1, *hWu1, *hWr1, *hWn1, *hWo2, *hWu2, *hWr2, *hWn2;
    cudaGetSymbolAddress((void**)&hWo1, g_hWo1);
    cudaGetSymbolAddress((void**)&hWu1, g_hWu1);
    cudaGetSymbolAddress((void**)&hWr1, g_hWr1);
    cudaGetSymbolAddress((void**)&hWn1, g_hWn1);
    cudaGetSymbolAddress((void**)&hWo2, g_hWo2);
    cudaGetSymbolAddress((void**)&hWu2, g_hWu2);
    cudaGetSymbolAddress((void**)&hWr2, g_hWr2);
    cudaGetSymbolAddress((void**)&hWn2, g_hWn2);

    pack_p1_kernel<<<200, 256>>>(Wo1, hWo1, 512);
    pack_p1_kernel<<<400, 256>>>(Wu1, hWu1, 1024);
    pack_p1_kernel<<<400, 256>>>(Wr1, hWr1, 1024);
    pack_p1_kernel<<<400, 256>>>(Wn1, hWn1, 1024);
    pack_p2_kernel<<<200, 256>>>(Wo2, hWo2, 512);
    pack_p2_kernel<<<200, 256>>>(Wu2, hWu2, 512);
    pack_p2_kernel<<<200, 256>>>(Wr2, hWr2, 512);
    pack_p2_kernel<<<400, 256>>>(Wn2, hWn2, 1024);

    dim3 pgrid(NT, 16);
    prep_xproj_kernel<<<pgrid, 256>>>(x, Wu1, bu1, Wr1, br1, Wn1, bn1);
    odegru_kernel<<<NB / 2, NTH>>>(xt,
        Wt1, bt1, Wt2, bt2, Wt3, bt3,
        bo1, bo2, bu2, br2, bn2, out);
}

// round 14
// speedup vs baseline: 1.2008x; 1.2008x over previous
#include <cuda_runtime.h>
#include <cuda_fp16.h>
#include <math.h>

// Problem constants: B=256, T=200, X=128, H=512, NU=100, cin=1152.
#define NB 256
#define NT 200
#define NX 128
#define NH 512
#define NTH 1024

// Device-global scratch (allocation-free).
__device__ float g_xpu[NT * NB * 100];
__device__ float g_xpr[NT * NB * 100];
__device__ float g_xpn[NT * NB * 100];

// fp16 weight streams.
// Phase-1 pack: uint4 at (k2, g) = rows (2k2,2k2+1) x cols (4g..4g+3):
//   idx = (k2*25 + (j>>2))*8 + (k&1)*4 + (j%4)
__device__ __half g_hWo1[512  * 100];
__device__ __half g_hWu1[1024 * 100];
__device__ __half g_hWr1[1024 * 100];
__device__ __half g_hWn1[1024 * 100];
// Phase-2 pack: half2 per (j2, col): idx = ((j>>1)*ncol + c)*2 + (j&1)
__device__ __half g_hWo2[100 * 512];
__device__ __half g_hWu2[100 * 512];
__device__ __half g_hWr2[100 * 512];
__device__ __half g_hWn2[100 * 1024];

// ---------------------------------------------------------------------------
__global__ void pack_p1_kernel(const float* __restrict__ src, __half* __restrict__ dst, int nrows) {
    int n = nrows * 100;
    for (int i = blockIdx.x * blockDim.x + threadIdx.x; i < n; i += gridDim.x * blockDim.x) {
        int k = i / 100, j = i % 100;
        dst[((k >> 1) * 25 + (j >> 2)) * 8 + (k & 1) * 4 + (j & 3)] = __float2half_rn(src[i]);
    }
}

__global__ void pack_p2_kernel(const float* __restrict__ src, __half* __restrict__ dst, int ncol) {
    int n = 100 * ncol;
    for (int i = blockIdx.x * blockDim.x + threadIdx.x; i < n; i += gridDim.x * blockDim.x) {
        int j = i / ncol, c = i % ncol;
        dst[(((j >> 1) * ncol) + c) * 2 + (j & 1)] = __float2half_rn(src[i]);
    }
}

// ---------------------------------------------------------------------------
// Prep: g_xp*[t][b][j] = b*1[j] + sum_i x[b][t][i] * W*1[(1024+i)*100 + j]  (fp32)
// ---------------------------------------------------------------------------
__global__ __launch_bounds__(256) void prep_xproj_kernel(
    const float* __restrict__ x,
    const float* __restrict__ Wu1, const float* __restrict__ bu1,
    const float* __restrict__ Wr1, const float* __restrict__ br1,
    const float* __restrict__ Wn1, const float* __restrict__ bn1)
{
    int t   = blockIdx.x;
    int bt  = blockIdx.y;
    int tid = threadIdx.x;
    if (tid >= 200) return;
    int j  = tid % 100;
    int s  = tid / 100;
    int b0 = bt * 16 + s * 8;

    float au[8], ar[8], an[8];
    float vbu = bu1[j], vbr = br1[j], vbn = bn1[j];
#pragma unroll
    for (int bi = 0; bi < 8; bi++) { au[bi] = vbu; ar[bi] = vbr; an[bi] = vbn; }

    for (int i = 0; i < NX; i += 4) {
        float wu[4], wr[4], wn[4];
#pragma unroll
        for (int c = 0; c < 4; c++) {
            int wi = (2 * NH + i + c) * 100 + j;
            wu[c] = __ldg(Wu1 + wi);
            wr[c] = __ldg(Wr1 + wi);
            wn[c] = __ldg(Wn1 + wi);
        }
#pragma unroll
        for (int bi = 0; bi < 8; bi++) {
            float4 xv = *reinterpret_cast<const float4*>(
                x + ((size_t)(b0 + bi) * NT + t) * NX + i);
            au[bi] += xv.x * wu[0] + xv.y * wu[1] + xv.z * wu[2] + xv.w * wu[3];
            ar[bi] += xv.x * wr[0] + xv.y * wr[1] + xv.z * wr[2] + xv.w * wr[3];
            an[bi] += xv.x * wn[0] + xv.y * wn[1] + xv.z * wn[2] + xv.w * wn[3];
        }
    }
#pragma unroll
    for (int bi = 0; bi < 8; bi++) {
        int idx = (t * NB + b0 + bi) * 100 + j;
        g_xpu[idx] = au[bi];
        g_xpr[idx] = ar[bi];
        g_xpn[idx] = an[bi];
    }
}

__device__ __forceinline__ float fast_tanh(float x) {
    float y;
    asm("tanh.approx.f32 %0, %1;" : "=f"(y) : "f"(x));
    return y;
}
__device__ __forceinline__ float sigm(float v) {
    return 0.5f * fast_tanh(0.5f * v) + 0.5f;
}

// Phase-1 fp16 MAC helper: one uint4 = 8 halves = rows (2k2,2k2+1) x cols (4g..4g+3)
#define P1_STEP(qptr, va, vb, ua, ub, acc0, acc1) do {                     \
    uint4 q = *reinterpret_cast<const uint4*>(qptr);                        \
    const __half2* hh = reinterpret_cast<const __half2*>(&q);               \
    float2 wa01 = __half22float2(hh[0]);                                    \
    float2 wa23 = __half22float2(hh[1]);                                    \
    float2 wb01 = __half22float2(hh[2]);                                    \
    float2 wb23 = __half22float2(hh[3]);                                    \
    acc0.x += va * wa01.x + vb * wb01.x;                                    \
    acc0.y += va * wa01.y + vb * wb01.y;                                    \
    acc0.z += va * wa23.x + vb * wb23.x;                                    \
    acc0.w += va * wa23.y + vb * wb23.y;                                    \
    acc1.x += ua * wa01.x + ub * wb01.x;                                    \
    acc1.y += ua * wa01.y + ub * wb01.y;                                    \
    acc1.z += ua * wa23.x + ub * wb23.x;                                    \
    acc1.w += ua * wa23.y + ub * wb23.y;                                    \
} while (0)

// ---------------------------------------------------------------------------
// Persistent recurrent kernel: 128 blocks x 1024 threads (32 warps/SM).
// fp16 weight streams + CVT + FFMA (proven R10 numerics), fp32 state.
// R14: biases staged in smem; A2 runs on all 1024 threads.
// ---------------------------------------------------------------------------
__global__ __launch_bounds__(NTH) void odegru_kernel(
    const float* __restrict__ xt,
    const float* __restrict__ Wt1, const float* __restrict__ bt1,
    const float* __restrict__ Wt2, const float* __restrict__ bt2,
    const float* __restrict__ Wt3, const float* __restrict__ bt3,
    const float* __restrict__ bo1, const float* __restrict__ bo2,
    const float* __restrict__ bu2, const float* __restrict__ br2,
    const float* __restrict__ bn2,
    float* __restrict__ out)
{
    __shared__ __align__(16) float sh_h [2][NH];
    __shared__ __align__(16) float sh_hs[2][NH];
    __shared__ __align__(16) float sh_ho[2][NH];
    __shared__ __align__(16) float sh_u [2][NH];
    __shared__ __align__(16) float sh_ch[2][NH];
    __shared__ __align__(16) float sh_cs[2][NH];
    __shared__ __align__(16) float sh_t1[2][100];
    __shared__ __align__(16) float sh_t2[2][100];
    __shared__ __align__(16) float sh_part[32 * 2 * 100];
    __shared__ float sh_dt[NT];
    // smem-staged biases (loop-invariant; avoids per-step L2 LDG in narrow phases)
    __shared__ float sb_bo1[100];
    __shared__ float sb_bo2[NH];
    __shared__ float sb_bu2[NH];
    __shared__ float sb_br2[NH];
    __shared__ float sb_bn2[2 * NH];

    const int tid = threadIdx.x;
    const int b0  = blockIdx.x * 2;

    // phase-1 mappings
    const int g25 = tid % 25;           // j-group: cols 4g..4g+3
    const int c32 = tid / 25;           // chunk 0..31 (tid<800)
    const int gateB = tid / 400;        // B1: 0=u, 1=r
    const int sB    = tid % 400;
    const int cB    = sB / 25;          // 0..15
    const int gB    = sB % 25;
    // reduce mappings
    const int rrow  = (tid / 100) & 1, rj = tid % 100;
    const int rgate = tid / 200;
    // phase-2 column mappings
    const int gcol  = tid >> 9;          // row for A2; gate/half for B2/C2/head
    const int col   = tid & 511;

    // init: dt table, biases, zero states
    if (tid < NT) {
        float v;
        if (tid == 0)      v = -0.01f;
        else if (tid == 1) v = xt[NT - 1] - xt[0];
        else               v = xt[tid - 2] - xt[tid - 1];
        sh_dt[tid] = v;
    }
    if (tid < 100) sb_bo1[tid] = bo1[tid];
    if (tid < NH) {
        sb_bo2[tid] = bo2[tid];
        sb_bu2[tid] = bu2[tid];
        sb_br2[tid] = br2[tid];
    }
    sb_bn2[tid] = bn2[tid];
    for (int k = tid; k < NH; k += NTH) {
        sh_h[0][k] = 0.f; sh_h[1][k] = 0.f;
        sh_hs[0][k] = 0.f; sh_hs[1][k] = 0.f;
    }
    __syncthreads();

    for (int t = 0; t < NT; t++) {
        const float dt = sh_dt[t];

        // Prefetch this step's x-projection values.
        float pf_ur = 0.f, pf_n = 0.f;
        if (tid < 400) {
            int idx = (t * NB + b0 + rrow) * 100 + rj;
            pf_ur = rgate ? __ldg(g_xpr + idx) : __ldg(g_xpu + idx);
            if (tid < 200) pf_n = __ldg(g_xpn + idx);
        }

        // ---- Phase A1: a = tanh(h @ Wo1 + bo1); 32 chunks x 8 k2 ----
        if (tid < 800) {
            float4 a0 = {0.f,0.f,0.f,0.f}, a1 = {0.f,0.f,0.f,0.f};
            const __half* wp = g_hWo1 + ((size_t)(c32 * 8) * 25 + g25) * 8;
            const float* s0 = &sh_h[0][c32 * 16];
            const float* s1 = &sh_h[1][c32 * 16];
#pragma unroll
            for (int k2 = 0; k2 < 8; k2++) {
                P1_STEP(wp, s0[2*k2], s0[2*k2+1], s1[2*k2], s1[2*k2+1], a0, a1);
                wp += 200;
            }
            *reinterpret_cast<float4*>(&sh_part[(c32 * 2 + 0) * 100 + 4 * g25]) = a0;
            *reinterpret_cast<float4*>(&sh_part[(c32 * 2 + 1) * 100 + 4 * g25]) = a1;
        }
        __syncthreads();
        if (tid < 200) {
            float s = sb_bo1[rj];
#pragma unroll
            for (int cc = 0; cc < 32; cc++) s += sh_part[(cc * 2 + rrow) * 100 + rj];
            sh_t1[rrow][rj] = fast_tanh(s);
        }
        __syncthreads();

        // ---- Phase A2: h_ode = h + dt*(a @ Wo2 + bo2); ALL 1024 threads,
        //      one (row,col) per thread (duplicated weight loads; latency-bound
        //      regime -> extra warps buy load cover) ----
        {
            float f = sb_bo2[col];
            const __half2* wp = reinterpret_cast<const __half2*>(g_hWo2) + col;
#pragma unroll 10
            for (int j2 = 0; j2 < 50; j2++) {
                float2 w = __half22float2(*wp); wp += NH;
                f += sh_t1[gcol][2*j2] * w.x + sh_t1[gcol][2*j2+1] * w.y;
            }
            sh_ho[gcol][col] = sh_h[gcol][col] + dt * f;
        }
        __syncthreads();

        // ---- Phase B1: tu/tr = tanh(xp + [ho,hs] @ W{u,r}1); 16 chunks x 32 k2 ----
        if (tid < 800) {
            float4 a0 = {0.f,0.f,0.f,0.f}, a1 = {0.f,0.f,0.f,0.f};
            const int kk0 = cB * 64;
            const __half* wp = (gateB ? g_hWr1 : g_hWu1) + ((size_t)(cB * 32) * 25 + gB) * 8;
            const float *sp0, *sp1;
            if (cB < 8) { sp0 = &sh_ho[0][kk0];      sp1 = &sh_ho[1][kk0]; }
            else        { sp0 = &sh_hs[0][kk0 - NH]; sp1 = &sh_hs[1][kk0 - NH]; }
#pragma unroll 8
            for (int k2 = 0; k2 < 32; k2++) {
                P1_STEP(wp, sp0[2*k2], sp0[2*k2+1], sp1[2*k2], sp1[2*k2+1], a0, a1);
                wp += 200;
            }
            *reinterpret_cast<float4*>(&sh_part[(cB * 4 + gateB * 2 + 0) * 100 + 4 * gB]) = a0;
            *reinterpret_cast<float4*>(&sh_part[(cB * 4 + gateB * 2 + 1) * 100 + 4 * gB]) = a1;
        }
        __syncthreads();
        if (tid < 400) {
            if (rgate == 0) {
                float su = pf_ur;
#pragma unroll
                for (int cc = 0; cc < 16; cc++) su += sh_part[(cc * 4 + rrow) * 100 + rj];
                sh_t1[rrow][rj] = fast_tanh(su);
            } else {
                float sr = pf_ur;
#pragma unroll
                for (int cc = 0; cc < 16; cc++) sr += sh_part[(cc * 4 + 2 + rrow) * 100 + rj];
                sh_t2[rrow][rj] = fast_tanh(sr);
            }
        }
        __syncthreads();

        // ---- Phase B2: u/r per column, both rows; gate-split halves ----
        if (gcol == 0) {
            float a0 = sb_bu2[col], a1 = a0;
            const __half2* wp = reinterpret_cast<const __half2*>(g_hWu2) + col;
#pragma unroll 10
            for (int j2 = 0; j2 < 50; j2++) {
                float2 w = __half22float2(*wp); wp += NH;
                a0 += sh_t1[0][2*j2] * w.x + sh_t1[0][2*j2+1] * w.y;
                a1 += sh_t1[1][2*j2] * w.x + sh_t1[1][2*j2+1] * w.y;
            }
            sh_u[0][col] = sigm(a0);
            sh_u[1][col] = sigm(a1);
        } else {
            float a0 = sb_br2[col], a1 = a0;
            const __half2* wp = reinterpret_cast<const __half2*>(g_hWr2) + col;
#pragma unroll 10
            for (int j2 = 0; j2 < 50; j2++) {
                float2 w = __half22float2(*wp); wp += NH;
                a0 += sh_t2[0][2*j2] * w.x + sh_t2[0][2*j2+1] * w.y;
                a1 += sh_t2[1][2*j2] * w.x + sh_t2[1][2*j2+1] * w.y;
            }
            float r0 = sigm(a0), r1 = sigm(a1);
            sh_ch[0][col] = sh_ho[0][col] * r0;
            sh_ch[1][col] = sh_ho[1][col] * r1;
            sh_cs[0][col] = sh_hs[0][col] * r0;
            sh_cs[1][col] = sh_hs[1][col] * r1;
        }
        __syncthreads();

        // ---- Phase C1: tn = tanh(xpn + [ch,cs] @ Wn1); 32 chunks x 16 k2 ----
        if (tid < 800) {
            float4 a0 = {0.f,0.f,0.f,0.f}, a1 = {0.f,0.f,0.f,0.f};
            const int kk0 = c32 * 32;
            const __half* wp = g_hWn1 + ((size_t)(c32 * 16) * 25 + g25) * 8;
            const float *sp0, *sp1;
            if (kk0 < NH) { sp0 = &sh_ch[0][kk0];      sp1 = &sh_ch[1][kk0]; }
            else          { sp0 = &sh_cs[0][kk0 - NH]; sp1 = &sh_cs[1][kk0 - NH]; }
#pragma unroll 8
            for (int k2 = 0; k2 < 16; k2++) {
                P1_STEP(wp, sp0[2*k2], sp0[2*k2+1], sp1[2*k2], sp1[2*k2+1], a0, a1);
                wp += 200;
            }
            *reinterpret_cast<float4*>(&sh_part[(c32 * 2 + 0) * 100 + 4 * g25]) = a0;
            *reinterpret_cast<float4*>(&sh_part[(c32 * 2 + 1) * 100 + 4 * g25]) = a1;
        }
        __syncthreads();
        if (tid < 200) {
            float sn = pf_n;
#pragma unroll
            for (int cc = 0; cc < 32; cc++) sn += sh_part[(cc * 2 + rrow) * 100 + rj];
            sh_t1[rrow][rj] = fast_tanh(sn);
        }
        __syncthreads();

        // ---- Phase C2: ns = tn @ Wn2 + bn2; m/s per column, both rows ----
        {
            float a0 = sb_bn2[gcol * NH + col], a1 = a0;
            const __half2* wp = reinterpret_cast<const __half2*>(g_hWn2) + gcol * NH + col;
#pragma unroll 10
            for (int j2 = 0; j2 < 50; j2++) {
                float2 w = __half22float2(*wp); wp += 2 * NH;
                a0 += sh_t1[0][2*j2] * w.x + sh_t1[0][2*j2+1] * w.y;
                a1 += sh_t1[1][2*j2] * w.x + sh_t1[1][2*j2+1] * w.y;
            }
            float u0 = sh_u[0][col], u1 = sh_u[1][col];
            if (gcol == 0) {
                sh_h[0][col] = (1.f - u0) * a0 + u0 * sh_ho[0][col];
                sh_h[1][col] = (1.f - u1) * a1 + u1 * sh_ho[1][col];
            } else {
                sh_hs[0][col] = (1.f - u0) * fabsf(a0) + u0 * sh_hs[0][col];
                sh_hs[1][col] = (1.f - u1) * fabsf(a1) + u1 * sh_hs[1][col];
            }
        }
        __syncthreads();
    }

    // ================= Final head (fp32, run once) =================
    if (tid < 800) {
        float4 a0 = {0.f,0.f,0.f,0.f}, a1 = {0.f,0.f,0.f,0.f};
        const int kk0 = c32 * 32;
        const float* wp = Wt1 + kk0 * 100 + 4 * g25;
        const float *sp0, *sp1;
        if (kk0 < NH) { sp0 = &sh_h[0][kk0];       sp1 = &sh_h[1][kk0]; }
        else          { sp0 = &sh_hs[0][kk0 - NH]; sp1 = &sh_hs[1][kk0 - NH]; }
#pragma unroll 8
        for (int kc = 0; kc < 32; kc++) {
            float4 w = *reinterpret_cast<const float4*>(wp); wp += 100;
            float v0 = sp0[kc], v1 = sp1[kc];
            a0.x += v0 * w.x; a0.y += v0 * w.y; a0.z += v0 * w.z; a0.w += v0 * w.w;
            a1.x += v1 * w.x; a1.y += v1 * w.y; a1.z += v1 * w.z; a1.w += v1 * w.w;
        }
        *reinterpret_cast<float4*>(&sh_part[(c32 * 2 + 0) * 100 + 4 * g25]) = a0;
        *reinterpret_cast<float4*>(&sh_part[(c32 * 2 + 1) * 100 + 4 * g25]) = a1;
    }
    __syncthreads();
    if (tid < 200) {
        float s = bt1[rj];
#pragma unroll
        for (int cc = 0; cc < 32; cc++) s += sh_part[(cc * 2 + rrow) * 100 + rj];
        sh_t1[rrow][rj] = tanhf(s);
    }
    __syncthreads();
    if (tid < 200) {
        float s = bt2[rj];
#pragma unroll 4
        for (int jj = 0; jj < 100; jj++) s += sh_t1[rrow][jj] * Wt2[jj * 100 + rj];
        sh_t2[rrow][rj] = tanhf(s);
    }
    __syncthreads();
    {
        float b = bt3[tid];
        float a0 = b, a1 = b;
        const float* wp = Wt3 + tid;
#pragma unroll 10
        for (int j = 0; j < 100; j++) {
            float w = *wp; wp += 2 * NH;
            a0 += sh_t2[0][j] * w;
            a1 += sh_t2[1][j] * w;
        }
        if (gcol == 0) {
            out[(size_t)(b0 + 0) * NH + col] = a0;
            out[(size_t)(b0 + 1) * NH + col] = a1;
        } else {
            out[(size_t)NB * NH + (size_t)(b0 + 0) * NH + col] = fabsf(a0);
            out[(size_t)NB * NH + (size_t)(b0 + 1) * NH + col] = fabsf(a1);
        }
    }
}

// ---------------------------------------------------------------------------
extern "C" void kernel_launch(void* const* d_in, const int* in_sizes, int n_in,
                              void* d_out, int out_size) {
    const float* x   = (const float*)d_in[0];
    const float* xt  = (const float*)d_in[1];
    const float* Wu1 = (const float*)d_in[2];
    const float* bu1 = (const float*)d_in[3];
    const float* Wu2 = (const float*)d_in[4];
    const float* bu2 = (const float*)d_in[5];
    const float* Wr1 = (const float*)d_in[6];
    const float* br1 = (const float*)d_in[7];
    const float* Wr2 = (const float*)d_in[8];
    const float* br2 = (const float*)d_in[9];
    const float* Wn1 = (const float*)d_in[10];
    const float* bn1 = (const float*)d_in[11];
    const float* Wn2 = (const float*)d_in[12];
    const float* bn2 = (const float*)d_in[13];
    const float* Wo1 = (const float*)d_in[14];
    const float* bo1 = (const float*)d_in[15];
    const float* Wo2 = (const float*)d_in[16];
    const float* bo2 = (const float*)d_in[17];
    const float* Wt1 = (const float*)d_in[18];
    const float* bt1 = (const float*)d_in[19];
    const float* Wt2 = (const float*)d_in[20];
    const float* bt2 = (const float*)d_in[21];
    const float* Wt3 = (const float*)d_in[22];
    const float* bt3 = (const float*)d_in[23];
    float* out = (float*)d_out;

    __half *hWo1, *hWu1, *hWr1, *hWn1, *hWo2, *hWu2, *hWr2, *hWn2;
    cudaGetSymbolAddress((void**)&hWo1, g_hWo1);
    cudaGetSymbolAddress((void**)&hWu1, g_hWu1);
    cudaGetSymbolAddress((void**)&hWr1, g_hWr1);
    cudaGetSymbolAddress((void**)&hWn1, g_hWn1);
    cudaGetSymbolAddress((void**)&hWo2, g_hWo2);
    cudaGetSymbolAddress((void**)&hWu2, g_hWu2);
    cudaGetSymbolAddress((void**)&hWr2, g_hWr2);
    cudaGetSymbolAddress((void**)&hWn2, g_hWn2);

    pack_p1_kernel<<<200, 256>>>(Wo1, hWo1, 512);
    pack_p1_kernel<<<400, 256>>>(Wu1, hWu1, 1024);
    pack_p1_kernel<<<400, 256>>>(Wr1, hWr1, 1024);
    pack_p1_kernel<<<400, 256>>>(Wn1, hWn1, 1024);
    pack_p2_kernel<<<200, 256>>>(Wo2, hWo2, 512);
    pack_p2_kernel<<<200, 256>>>(Wu2, hWu2, 512);
    pack_p2_kernel<<<200, 256>>>(Wr2, hWr2, 512);
    pack_p2_kernel<<<400, 256>>>(Wn2, hWn2, 1024);

    dim3 pgrid(NT, 16);
    prep_xproj_kernel<<<pgrid, 256>>>(x, Wu1, bu1, Wr1, br1, Wn1, bn1);
    odegru_kernel<<<NB / 2, NTH>>>(xt,
        Wt1, bt1, Wt2, bt2, Wt3, bt3,
        bo1, bo2, bu2, br2, bn2, out);
}

// round 15
// speedup vs baseline: 1.4144x; 1.1779x over previous
#include <cuda_runtime.h>
#include <cuda_fp16.h>
#include <math.h>

// Problem constants: B=256, T=200, X=128, H=512, NU=100, cin=1152.
#define NB 256
#define NT 200
#define NX 128
#define NH 512
#define NTH 1024

// Device-global scratch (allocation-free).
__device__ float g_xpu[NT * NB * 100];
__device__ float g_xpr[NT * NB * 100];
__device__ float g_xpn[NT * NB * 100];

// fp16 weight streams.
// Phase-1 pack: uint4 at (k2, g) = rows (2k2,2k2+1) x cols (4g..4g+3):
//   idx = (k2*25 + (j>>2))*8 + (k&1)*4 + (j%4)
__device__ __half g_hWo1[512  * 100];
__device__ __half g_hWu1[1024 * 100];
__device__ __half g_hWr1[1024 * 100];
__device__ __half g_hWn1[1024 * 100];
// Phase-2 pack: half2 per (j2, col): idx = ((j>>1)*ncol + c)*2 + (j&1)
__device__ __half g_hWo2[100 * 512];
__device__ __half g_hWu2[100 * 512];
__device__ __half g_hWr2[100 * 512];
__device__ __half g_hWn2[100 * 1024];

// ---------------------------------------------------------------------------
__global__ void pack_p1_kernel(const float* __restrict__ src, __half* __restrict__ dst, int nrows) {
    int n = nrows * 100;
    for (int i = blockIdx.x * blockDim.x + threadIdx.x; i < n; i += gridDim.x * blockDim.x) {
        int k = i / 100, j = i % 100;
        dst[((k >> 1) * 25 + (j >> 2)) * 8 + (k & 1) * 4 + (j & 3)] = __float2half_rn(src[i]);
    }
}

__global__ void pack_p2_kernel(const float* __restrict__ src, __half* __restrict__ dst, int ncol) {
    int n = 100 * ncol;
    for (int i = blockIdx.x * blockDim.x + threadIdx.x; i < n; i += gridDim.x * blockDim.x) {
        int j = i / ncol, c = i % ncol;
        dst[(((j >> 1) * ncol) + c) * 2 + (j & 1)] = __float2half_rn(src[i]);
    }
}

// ---------------------------------------------------------------------------
// Prep: g_xp*[t][b][j] = b*1[j] + sum_i x[b][t][i] * W*1[(1024+i)*100 + j]  (fp32)
// ---------------------------------------------------------------------------
__global__ __launch_bounds__(256) void prep_xproj_kernel(
    const float* __restrict__ x,
    const float* __restrict__ Wu1, const float* __restrict__ bu1,
    const float* __restrict__ Wr1, const float* __restrict__ br1,
    const float* __restrict__ Wn1, const float* __restrict__ bn1)
{
    int t   = blockIdx.x;
    int bt  = blockIdx.y;
    int tid = threadIdx.x;
    if (tid >= 200) return;
    int j  = tid % 100;
    int s  = tid / 100;
    int b0 = bt * 16 + s * 8;

    float au[8], ar[8], an[8];
    float vbu = bu1[j], vbr = br1[j], vbn = bn1[j];
#pragma unroll
    for (int bi = 0; bi < 8; bi++) { au[bi] = vbu; ar[bi] = vbr; an[bi] = vbn; }

    for (int i = 0; i < NX; i += 4) {
        float wu[4], wr[4], wn[4];
#pragma unroll
        for (int c = 0; c < 4; c++) {
            int wi = (2 * NH + i + c) * 100 + j;
            wu[c] = __ldg(Wu1 + wi);
            wr[c] = __ldg(Wr1 + wi);
            wn[c] = __ldg(Wn1 + wi);
        }
#pragma unroll
        for (int bi = 0; bi < 8; bi++) {
            float4 xv = *reinterpret_cast<const float4*>(
                x + ((size_t)(b0 + bi) * NT + t) * NX + i);
            au[bi] += xv.x * wu[0] + xv.y * wu[1] + xv.z * wu[2] + xv.w * wu[3];
            ar[bi] += xv.x * wr[0] + xv.y * wr[1] + xv.z * wr[2] + xv.w * wr[3];
            an[bi] += xv.x * wn[0] + xv.y * wn[1] + xv.z * wn[2] + xv.w * wn[3];
        }
    }
#pragma unroll
    for (int bi = 0; bi < 8; bi++) {
        int idx = (t * NB + b0 + bi) * 100 + j;
        g_xpu[idx] = au[bi];
        g_xpr[idx] = ar[bi];
        g_xpn[idx] = an[bi];
    }
}

__device__ __forceinline__ float fast_tanh(float x) {
    float y;
    asm("tanh.approx.f32 %0, %1;" : "=f"(y) : "f"(x));
    return y;
}
__device__ __forceinline__ float sigm(float v) {
    return 0.5f * fast_tanh(0.5f * v) + 0.5f;
}
__device__ __forceinline__ void promote(float& af, __half2& ah) {
    float2 f = __half22float2(ah);
    af += f.x + f.y;
    ah = __float2half2_rn(0.f);
}

// Phase-1 fp16 MAC helper: one uint4 = 8 halves = rows (2k2,2k2+1) x cols (4g..4g+3)
#define P1_STEP(qptr, va, vb, ua, ub, acc0, acc1) do {                     \
    uint4 q = *reinterpret_cast<const uint4*>(qptr);                        \
    const __half2* hh = reinterpret_cast<const __half2*>(&q);               \
    float2 wa01 = __half22float2(hh[0]);                                    \
    float2 wa23 = __half22float2(hh[1]);                                    \
    float2 wb01 = __half22float2(hh[2]);                                    \
    float2 wb23 = __half22float2(hh[3]);                                    \
    acc0.x += va * wa01.x + vb * wb01.x;                                    \
    acc0.y += va * wa01.y + vb * wb01.y;                                    \
    acc0.z += va * wa23.x + vb * wb23.x;                                    \
    acc0.w += va * wa23.y + vb * wb23.y;                                    \
    acc1.x += ua * wa01.x + ub * wb01.x;                                    \
    acc1.y += ua * wa01.y + ub * wb01.y;                                    \
    acc1.z += ua * wa23.x + ub * wb23.x;                                    \
    acc1.w += ua * wa23.y + ub * wb23.y;                                    \
} while (0)

// ---------------------------------------------------------------------------
// Persistent recurrent kernel: 128 blocks x 1024 threads (32 warps/SM).
// Phase-1: fp16 weights + CVT + FFMA, fp32 state (proven R14 path).
// Phase-2: native HFMA2 on fp16 weights x fp16 activation vectors
//          (t-vectors written as fp16 by the reduce phases at zero extra cost),
//          fp32 promotion every 10 j-pairs (proven R13 phase-2 numerics).
// ---------------------------------------------------------------------------
__global__ __launch_bounds__(NTH) void odegru_kernel(
    const float* __restrict__ xt,
    const float* __restrict__ Wt1, const float* __restrict__ bt1,
    const float* __restrict__ Wt2, const float* __restrict__ bt2,
    const float* __restrict__ Wt3, const float* __restrict__ bt3,
    const float* __restrict__ bo1, const float* __restrict__ bo2,
    const float* __restrict__ bu2, const float* __restrict__ br2,
    const float* __restrict__ bn2,
    float* __restrict__ out)
{
    __shared__ __align__(16) float sh_h [2][NH];
    __shared__ __align__(16) float sh_hs[2][NH];
    __shared__ __align__(16) float sh_ho[2][NH];
    __shared__ __align__(16) float sh_u [2][NH];
    __shared__ __align__(16) float sh_ch[2][NH];
    __shared__ __align__(16) float sh_cs[2][NH];
    __shared__ __align__(16) float sh_t1[2][100];   // head only (fp32)
    __shared__ __align__(16) float sh_t2[2][100];   // head only (fp32)
    __shared__ __align__(16) float sh_part[32 * 2 * 100];
    __shared__ float sh_dt[NT];
    // fp16 activation vectors for phase-2 HFMA2 ([row][j2] as half2)
    __shared__ __align__(8) __half2 sh16_t1[2][50];
    __shared__ __align__(8) __half2 sh16_t2[2][50];
    // smem-staged biases
    __shared__ float sb_bo1[100];
    __shared__ float sb_bo2[NH];
    __shared__ float sb_bu2[NH];
    __shared__ float sb_br2[NH];
    __shared__ float sb_bn2[2 * NH];

    const int tid = threadIdx.x;
    const int b0  = blockIdx.x * 2;
    const __half2 hz = __float2half2_rn(0.f);

    // phase-1 mappings
    const int g25 = tid % 25;           // j-group: cols 4g..4g+3
    const int c32 = tid / 25;           // chunk 0..31 (tid<800)
    const int gateB = tid / 400;        // B1: 0=u, 1=r
    const int sB    = tid % 400;
    const int cB    = sB / 25;          // 0..15
    const int gB    = sB % 25;
    // reduce mappings
    const int rrow  = (tid / 100) & 1, rj = tid % 100;
    const int rgate = tid / 200;
    // phase-2 column mappings
    const int gcol  = tid >> 9;          // row for A2; gate/half for B2/C2/head
    const int col   = tid & 511;

    // init: dt table, biases, zero states
    if (tid < NT) {
        float v;
        if (tid == 0)      v = -0.01f;
        else if (tid == 1) v = xt[NT - 1] - xt[0];
        else               v = xt[tid - 2] - xt[tid - 1];
        sh_dt[tid] = v;
    }
    if (tid < 100) sb_bo1[tid] = bo1[tid];
    if (tid < NH) {
        sb_bo2[tid] = bo2[tid];
        sb_bu2[tid] = bu2[tid];
        sb_br2[tid] = br2[tid];
    }
    sb_bn2[tid] = bn2[tid];
    for (int k = tid; k < NH; k += NTH) {
        sh_h[0][k] = 0.f; sh_h[1][k] = 0.f;
        sh_hs[0][k] = 0.f; sh_hs[1][k] = 0.f;
    }
    __syncthreads();

    for (int t = 0; t < NT; t++) {
        const float dt = sh_dt[t];

        // Prefetch this step's x-projection values.
        float pf_ur = 0.f, pf_n = 0.f;
        if (tid < 400) {
            int idx = (t * NB + b0 + rrow) * 100 + rj;
            pf_ur = rgate ? __ldg(g_xpr + idx) : __ldg(g_xpu + idx);
            if (tid < 200) pf_n = __ldg(g_xpn + idx);
        }

        // ---- Phase A1: a = tanh(h @ Wo1 + bo1); 32 chunks x 8 k2 ----
        if (tid < 800) {
            float4 a0 = {0.f,0.f,0.f,0.f}, a1 = {0.f,0.f,0.f,0.f};
            const __half* wp = g_hWo1 + ((size_t)(c32 * 8) * 25 + g25) * 8;
            const float* s0 = &sh_h[0][c32 * 16];
            const float* s1 = &sh_h[1][c32 * 16];
#pragma unroll
            for (int k2 = 0; k2 < 8; k2++) {
                P1_STEP(wp, s0[2*k2], s0[2*k2+1], s1[2*k2], s1[2*k2+1], a0, a1);
                wp += 200;
            }
            *reinterpret_cast<float4*>(&sh_part[(c32 * 2 + 0) * 100 + 4 * g25]) = a0;
            *reinterpret_cast<float4*>(&sh_part[(c32 * 2 + 1) * 100 + 4 * g25]) = a1;
        }
        __syncthreads();
        if (tid < 200) {
            float s = sb_bo1[rj];
#pragma unroll
            for (int cc = 0; cc < 32; cc++) s += sh_part[(cc * 2 + rrow) * 100 + rj];
            reinterpret_cast<__half*>(&sh16_t1[rrow][0])[rj] = __float2half_rn(fast_tanh(s));
        }
        __syncthreads();

        // ---- Phase A2: h_ode = h + dt*(a @ Wo2 + bo2); ALL 1024 threads,
        //      one (row,col) per thread; HFMA2 with promotion every 10 j2 ----
        {
            float f = sb_bo2[col];
            __half2 a = hz;
            const __half2* wp = reinterpret_cast<const __half2*>(g_hWo2) + col;
            const __half2* tp = &sh16_t1[gcol][0];
#pragma unroll
            for (int run = 0; run < 5; run++) {
#pragma unroll
                for (int jj = 0; jj < 10; jj++) {
                    a = __hfma2(tp[run * 10 + jj], *wp, a);
                    wp += NH;
                }
                promote(f, a);
            }
            sh_ho[gcol][col] = sh_h[gcol][col] + dt * f;
        }
        __syncthreads();

        // ---- Phase B1: tu/tr = tanh(xp + [ho,hs] @ W{u,r}1); 16 chunks x 32 k2 ----
        if (tid < 800) {
            float4 a0 = {0.f,0.f,0.f,0.f}, a1 = {0.f,0.f,0.f,0.f};
            const int kk0 = cB * 64;
            const __half* wp = (gateB ? g_hWr1 : g_hWu1) + ((size_t)(cB * 32) * 25 + gB) * 8;
            const float *sp0, *sp1;
            if (cB < 8) { sp0 = &sh_ho[0][kk0];      sp1 = &sh_ho[1][kk0]; }
            else        { sp0 = &sh_hs[0][kk0 - NH]; sp1 = &sh_hs[1][kk0 - NH]; }
#pragma unroll 8
            for (int k2 = 0; k2 < 32; k2++) {
                P1_STEP(wp, sp0[2*k2], sp0[2*k2+1], sp1[2*k2], sp1[2*k2+1], a0, a1);
                wp += 200;
            }
            *reinterpret_cast<float4*>(&sh_part[(cB * 4 + gateB * 2 + 0) * 100 + 4 * gB]) = a0;
            *reinterpret_cast<float4*>(&sh_part[(cB * 4 + gateB * 2 + 1) * 100 + 4 * gB]) = a1;
        }
        __syncthreads();
        if (tid < 400) {
            if (rgate == 0) {
                float su = pf_ur;
#pragma unroll
                for (int cc = 0; cc < 16; cc++) su += sh_part[(cc * 4 + rrow) * 100 + rj];
                reinterpret_cast<__half*>(&sh16_t1[rrow][0])[rj] = __float2half_rn(fast_tanh(su));
            } else {
                float sr = pf_ur;
#pragma unroll
                for (int cc = 0; cc < 16; cc++) sr += sh_part[(cc * 4 + 2 + rrow) * 100 + rj];
                reinterpret_cast<__half*>(&sh16_t2[rrow][0])[rj] = __float2half_rn(fast_tanh(sr));
            }
        }
        __syncthreads();

        // ---- Phase B2: u/r per column, both rows; HFMA2, gate-split halves ----
        if (gcol == 0) {
            float f0 = sb_bu2[col], f1 = f0;
            __half2 a0 = hz, a1 = hz;
            const __half2* wp = reinterpret_cast<const __half2*>(g_hWu2) + col;
#pragma unroll
            for (int run = 0; run < 5; run++) {
#pragma unroll
                for (int jj = 0; jj < 10; jj++) {
                    __half2 w = *wp; wp += NH;
                    a0 = __hfma2(sh16_t1[0][run * 10 + jj], w, a0);
                    a1 = __hfma2(sh16_t1[1][run * 10 + jj], w, a1);
                }
                promote(f0, a0); promote(f1, a1);
            }
            sh_u[0][col] = sigm(f0);
            sh_u[1][col] = sigm(f1);
        } else {
            float f0 = sb_br2[col], f1 = f0;
            __half2 a0 = hz, a1 = hz;
            const __half2* wp = reinterpret_cast<const __half2*>(g_hWr2) + col;
#pragma unroll
            for (int run = 0; run < 5; run++) {
#pragma unroll
                for (int jj = 0; jj < 10; jj++) {
                    __half2 w = *wp; wp += NH;
                    a0 = __hfma2(sh16_t2[0][run * 10 + jj], w, a0);
                    a1 = __hfma2(sh16_t2[1][run * 10 + jj], w, a1);
                }
                promote(f0, a0); promote(f1, a1);
            }
            float r0 = sigm(f0), r1 = sigm(f1);
            sh_ch[0][col] = sh_ho[0][col] * r0;
            sh_ch[1][col] = sh_ho[1][col] * r1;
            sh_cs[0][col] = sh_hs[0][col] * r0;
            sh_cs[1][col] = sh_hs[1][col] * r1;
        }
        __syncthreads();

        // ---- Phase C1: tn = tanh(xpn + [ch,cs] @ Wn1); 32 chunks x 16 k2 ----
        if (tid < 800) {
            float4 a0 = {0.f,0.f,0.f,0.f}, a1 = {0.f,0.f,0.f,0.f};
            const int kk0 = c32 * 32;
            const __half* wp = g_hWn1 + ((size_t)(c32 * 16) * 25 + g25) * 8;
            const float *sp0, *sp1;
            if (kk0 < NH) { sp0 = &sh_ch[0][kk0];      sp1 = &sh_ch[1][kk0]; }
            else          { sp0 = &sh_cs[0][kk0 - NH]; sp1 = &sh_cs[1][kk0 - NH]; }
#pragma unroll 8
            for (int k2 = 0; k2 < 16; k2++) {
                P1_STEP(wp, sp0[2*k2], sp0[2*k2+1], sp1[2*k2], sp1[2*k2+1], a0, a1);
                wp += 200;
            }
            *reinterpret_cast<float4*>(&sh_part[(c32 * 2 + 0) * 100 + 4 * g25]) = a0;
            *reinterpret_cast<float4*>(&sh_part[(c32 * 2 + 1) * 100 + 4 * g25]) = a1;
        }
        __syncthreads();
        if (tid < 200) {
            float sn = pf_n;
#pragma unroll
            for (int cc = 0; cc < 32; cc++) sn += sh_part[(cc * 2 + rrow) * 100 + rj];
            reinterpret_cast<__half*>(&sh16_t1[rrow][0])[rj] = __float2half_rn(fast_tanh(sn));
        }
        __syncthreads();

        // ---- Phase C2: ns = tn @ Wn2 + bn2; m/s per column; HFMA2 ----
        {
            float f0 = sb_bn2[gcol * NH + col], f1 = f0;
            __half2 a0 = hz, a1 = hz;
            const __half2* wp = reinterpret_cast<const __half2*>(g_hWn2) + gcol * NH + col;
#pragma unroll
            for (int run = 0; run < 5; run++) {
#pragma unroll
                for (int jj = 0; jj < 10; jj++) {
                    __half2 w = *wp; wp += 2 * NH;
                    a0 = __hfma2(sh16_t1[0][run * 10 + jj], w, a0);
                    a1 = __hfma2(sh16_t1[1][run * 10 + jj], w, a1);
                }
                promote(f0, a0); promote(f1, a1);
            }
            float u0 = sh_u[0][col], u1 = sh_u[1][col];
            if (gcol == 0) {
                sh_h[0][col] = (1.f - u0) * f0 + u0 * sh_ho[0][col];
                sh_h[1][col] = (1.f - u1) * f1 + u1 * sh_ho[1][col];
            } else {
                sh_hs[0][col] = (1.f - u0) * fabsf(f0) + u0 * sh_hs[0][col];
                sh_hs[1][col] = (1.f - u1) * fabsf(f1) + u1 * sh_hs[1][col];
            }
        }
        __syncthreads();
    }

    // ================= Final head (fp32, run once) =================
    if (tid < 800) {
        float4 a0 = {0.f,0.f,0.f,0.f}, a1 = {0.f,0.f,0.f,0.f};
        const int kk0 = c32 * 32;
        const float* wp = Wt1 + kk0 * 100 + 4 * g25;
        const float *sp0, *sp1;
        if (kk0 < NH) { sp0 = &sh_h[0][kk0];       sp1 = &sh_h[1][kk0]; }
        else          { sp0 = &sh_hs[0][kk0 - NH]; sp1 = &sh_hs[1][kk0 - NH]; }
#pragma unroll 8
        for (int kc = 0; kc < 32; kc++) {
            float4 w = *reinterpret_cast<const float4*>(wp); wp += 100;
            float v0 = sp0[kc], v1 = sp1[kc];
            a0.x += v0 * w.x; a0.y += v0 * w.y; a0.z += v0 * w.z; a0.w += v0 * w.w;
            a1.x += v1 * w.x; a1.y += v1 * w.y; a1.z += v1 * w.z; a1.w += v1 * w.w;
        }
        *reinterpret_cast<float4*>(&sh_part[(c32 * 2 + 0) * 100 + 4 * g25]) = a0;
        *reinterpret_cast<float4*>(&sh_part[(c32 * 2 + 1) * 100 + 4 * g25]) = a1;
    }
    __syncthreads();
    if (tid < 200) {
        float s = bt1[rj];
#pragma unroll
        for (int cc = 0; cc < 32; cc++) s += sh_part[(cc * 2 + rrow) * 100 + rj];
        sh_t1[rrow][rj] = tanhf(s);
    }
    __syncthreads();
    if (tid < 200) {
        float s = bt2[rj];
#pragma unroll 4
        for (int jj = 0; jj < 100; jj++) s += sh_t1[rrow][jj] * Wt2[jj * 100 + rj];
        sh_t2[rrow][rj] = tanhf(s);
    }
    __syncthreads();
    {
        float b = bt3[tid];
        float a0 = b, a1 = b;
        const float* wp = Wt3 + tid;
#pragma unroll 10
        for (int j = 0; j < 100; j++) {
            float w = *wp; wp += 2 * NH;
            a0 += sh_t2[0][j] * w;
            a1 += sh_t2[1][j] * w;
        }
        if (gcol == 0) {
            out[(size_t)(b0 + 0) * NH + col] = a0;
            out[(size_t)(b0 + 1) * NH + col] = a1;
        } else {
            out[(size_t)NB * NH + (size_t)(b0 + 0) * NH + col] = fabsf(a0);
            out[(size_t)NB * NH + (size_t)(b0 + 1) * NH + col] = fabsf(a1);
        }
    }
}

// ---------------------------------------------------------------------------
extern "C" void kernel_launch(void* const* d_in, const int* in_sizes, int n_in,
                              void* d_out, int out_size) {
    const float* x   = (const float*)d_in[0];
    const float* xt  = (const float*)d_in[1];
    const float* Wu1 = (const float*)d_in[2];
    const float* bu1 = (const float*)d_in[3];
    const float* Wu2 = (const float*)d_in[4];
    const float* bu2 = (const float*)d_in[5];
    const float* Wr1 = (const float*)d_in[6];
    const float* br1 = (const float*)d_in[7];
    const float* Wr2 = (const float*)d_in[8];
    const float* br2 = (const float*)d_in[9];
    const float* Wn1 = (const float*)d_in[10];
    const float* bn1 = (const float*)d_in[11];
    const float* Wn2 = (const float*)d_in[12];
    const float* bn2 = (const float*)d_in[13];
    const float* Wo1 = (const float*)d_in[14];
    const float* bo1 = (const float*)d_in[15];
    const float* Wo2 = (const float*)d_in[16];
    const float* bo2 = (const float*)d_in[17];
    const float* Wt1 = (const float*)d_in[18];
    const float* bt1 = (const float*)d_in[19];
    const float* Wt2 = (const float*)d_in[20];
    const float* bt2 = (const float*)d_in[21];
    const float* Wt3 = (const float*)d_in[22];
    const float* bt3 = (const float*)d_in[23];
    float* out = (float*)d_out;

    __half *hWo1, *hWu1, *hWr1, *hWn1, *hWo2, *hWu2, *hWr2, *hWn2;
    cudaGetSymbolAddress((void**)&hWo1, g_hWo1);
    cudaGetSymbolAddress((void**)&hWu1, g_hWu1);
    cudaGetSymbolAddress((void**)&hWr1, g_hWr1);
    cudaGetSymbolAddress((void**)&hWn1, g_hWn1);
    cudaGetSymbolAddress((void**)&hWo2, g_hWo2);
    cudaGetSymbolAddress((void**)&hWu2, g_hWu2);
    cudaGetSymbolAddress((void**)&hWr2, g_hWr2);
    cudaGetSymbolAddress((void**)&hWn2, g_hWn2);

    pack_p1_kernel<<<200, 256>>>(Wo1, hWo1, 512);
    pack_p1_kernel<<<400, 256>>>(Wu1, hWu1, 1024);
    pack_p1_kernel<<<400, 256>>>(Wr1, hWr1, 1024);
    pack_p1_kernel<<<400, 256>>>(Wn1, hWn1, 1024);
    pack_p2_kernel<<<200, 256>>>(Wo2, hWo2, 512);
    pack_p2_kernel<<<200, 256>>>(Wu2, hWu2, 512);
    pack_p2_kernel<<<200, 256>>>(Wr2, hWr2, 512);
    pack_p2_kernel<<<400, 256>>>(Wn2, hWn2, 1024);

    dim3 pgrid(NT, 16);
    prep_xproj_kernel<<<pgrid, 256>>>(x, Wu1, bu1, Wr1, br1, Wn1, bn1);
    odegru_kernel<<<NB / 2, NTH>>>(xt,
        Wt1, bt1, Wt2, bt2, Wt3, bt3,
        bo1, bo2, bu2, br2, bn2, out);
}

// round 16
// speedup vs baseline: 1.4872x; 1.0515x over previous
#include <cuda_runtime.h>
#include <cuda_fp16.h>
#include <math.h>

// Problem constants: B=256, T=200, X=128, H=512, NU=100, cin=1152.
#define NB 256
#define NT 200
#define NX 128
#define NH 512
#define NTH 1024

// Device-global scratch (allocation-free).
__device__ float g_xpu[NT * NB * 100];
__device__ float g_xpr[NT * NB * 100];
__device__ float g_xpn[NT * NB * 100];

// fp16 weight streams.
// Phase-1 pack: uint4 at (k2, g): halves [k-even](j0,j1,j2,j3) [k-odd](j0,j1,j2,j3)
//   -> as half2: (j0,j1)e, (j2,j3)e, (j0,j1)o, (j2,j3)o
//   idx = (k2*25 + (j>>2))*8 + (k&1)*4 + (j%4)
__device__ __half g_hWo1[512  * 100];
__device__ __half g_hWu1[1024 * 100];
__device__ __half g_hWr1[1024 * 100];
__device__ __half g_hWn1[1024 * 100];
// Phase-2 pack: half2 per (j2, col): idx = ((j>>1)*ncol + c)*2 + (j&1)
__device__ __half g_hWo2[100 * 512];
__device__ __half g_hWu2[100 * 512];
__device__ __half g_hWr2[100 * 512];
__device__ __half g_hWn2[100 * 1024];

// ---------------------------------------------------------------------------
__global__ void pack_p1_kernel(const float* __restrict__ src, __half* __restrict__ dst, int nrows) {
    int n = nrows * 100;
    for (int i = blockIdx.x * blockDim.x + threadIdx.x; i < n; i += gridDim.x * blockDim.x) {
        int k = i / 100, j = i % 100;
        dst[((k >> 1) * 25 + (j >> 2)) * 8 + (k & 1) * 4 + (j & 3)] = __float2half_rn(src[i]);
    }
}

__global__ void pack_p2_kernel(const float* __restrict__ src, __half* __restrict__ dst, int ncol) {
    int n = 100 * ncol;
    for (int i = blockIdx.x * blockDim.x + threadIdx.x; i < n; i += gridDim.x * blockDim.x) {
        int j = i / ncol, c = i % ncol;
        dst[(((j >> 1) * ncol) + c) * 2 + (j & 1)] = __float2half_rn(src[i]);
    }
}

// ---------------------------------------------------------------------------
// Prep: g_xp*[t][b][j] = b*1[j] + sum_i x[b][t][i] * W*1[(1024+i)*100 + j]  (fp32)
// ---------------------------------------------------------------------------
__global__ __launch_bounds__(256) void prep_xproj_kernel(
    const float* __restrict__ x,
    const float* __restrict__ Wu1, const float* __restrict__ bu1,
    const float* __restrict__ Wr1, const float* __restrict__ br1,
    const float* __restrict__ Wn1, const float* __restrict__ bn1)
{
    int t   = blockIdx.x;
    int bt  = blockIdx.y;
    int tid = threadIdx.x;
    if (tid >= 200) return;
    int j  = tid % 100;
    int s  = tid / 100;
    int b0 = bt * 16 + s * 8;

    float au[8], ar[8], an[8];
    float vbu = bu1[j], vbr = br1[j], vbn = bn1[j];
#pragma unroll
    for (int bi = 0; bi < 8; bi++) { au[bi] = vbu; ar[bi] = vbr; an[bi] = vbn; }

    for (int i = 0; i < NX; i += 4) {
        float wu[4], wr[4], wn[4];
#pragma unroll
        for (int c = 0; c < 4; c++) {
            int wi = (2 * NH + i + c) * 100 + j;
            wu[c] = __ldg(Wu1 + wi);
            wr[c] = __ldg(Wr1 + wi);
            wn[c] = __ldg(Wn1 + wi);
        }
#pragma unroll
        for (int bi = 0; bi < 8; bi++) {
            float4 xv = *reinterpret_cast<const float4*>(
                x + ((size_t)(b0 + bi) * NT + t) * NX + i);
            au[bi] += xv.x * wu[0] + xv.y * wu[1] + xv.z * wu[2] + xv.w * wu[3];
            ar[bi] += xv.x * wr[0] + xv.y * wr[1] + xv.z * wr[2] + xv.w * wr[3];
            an[bi] += xv.x * wn[0] + xv.y * wn[1] + xv.z * wn[2] + xv.w * wn[3];
        }
    }
#pragma unroll
    for (int bi = 0; bi < 8; bi++) {
        int idx = (t * NB + b0 + bi) * 100 + j;
        g_xpu[idx] = au[bi];
        g_xpr[idx] = ar[bi];
        g_xpn[idx] = an[bi];
    }
}

__device__ __forceinline__ float fast_tanh(float x) {
    float y;
    asm("tanh.approx.f32 %0, %1;" : "=f"(y) : "f"(x));
    return y;
}
__device__ __forceinline__ float sigm(float v) {
    return 0.5f * fast_tanh(0.5f * v) + 0.5f;
}
// Lane-separate promotion (lanes = distinct output columns).
__device__ __forceinline__ void promote2(float& ax, float& ay, __half2& ah) {
    float2 f = __half22float2(ah);
    ax += f.x; ay += f.y;
    ah = __float2half2_rn(0.f);
}
// Lane-summed promotion (phase-2: lanes = j-pair of same column).
__device__ __forceinline__ void promote(float& af, __half2& ah) {
    float2 f = __half22float2(ah);
    af += f.x + f.y;
    ah = __float2half2_rn(0.f);
}

// Phase-1 HFMA2 step: one uint4 = 2 k's x 4 cols; states are dup-half2.
// 16 MACs in 8 HFMA2 + 1 LDG.128 + 4 LDS.32.
#define P1H_STEP(qptr, s0e, s0o, s1e, s1o, A00, A01, A10, A11) do {        \
    uint4 q = *reinterpret_cast<const uint4*>(qptr);                        \
    __half2 w0 = *reinterpret_cast<__half2*>(&q.x);                         \
    __half2 w1 = *reinterpret_cast<__half2*>(&q.y);                         \
    __half2 w2 = *reinterpret_cast<__half2*>(&q.z);                         \
    __half2 w3 = *reinterpret_cast<__half2*>(&q.w);                         \
    A00 = __hfma2(s0e, w0, A00); A01 = __hfma2(s0e, w1, A01);               \
    A00 = __hfma2(s0o, w2, A00); A01 = __hfma2(s0o, w3, A01);               \
    A10 = __hfma2(s1e, w0, A10); A11 = __hfma2(s1e, w1, A11);               \
    A10 = __hfma2(s1o, w2, A10); A11 = __hfma2(s1o, w3, A11);               \
} while (0)

// ---------------------------------------------------------------------------
// Persistent recurrent kernel: 128 blocks x 1024 threads (32 warps/SM).
// Phase-1 AND phase-2 in HFMA2 (fp16 weights x fp16 activations), fp32 master
// state + blending; fp16 dup-half2 state shadows written where produced.
// ---------------------------------------------------------------------------
__global__ __launch_bounds__(NTH) void odegru_kernel(
    const float* __restrict__ xt,
    const float* __restrict__ Wt1, const float* __restrict__ bt1,
    const float* __restrict__ Wt2, const float* __restrict__ bt2,
    const float* __restrict__ Wt3, const float* __restrict__ bt3,
    const float* __restrict__ bo1, const float* __restrict__ bo2,
    const float* __restrict__ bu2, const float* __restrict__ br2,
    const float* __restrict__ bn2,
    float* __restrict__ out)
{
    // fp32 master state
    __shared__ __align__(16) float sh_h [2][NH];
    __shared__ __align__(16) float sh_hs[2][NH];
    __shared__ __align__(16) float sh_ho[2][NH];
    __shared__ __align__(16) float sh_u [2][NH];
    __shared__ __align__(16) float sh_t1[2][100];   // head only (fp32)
    __shared__ __align__(16) float sh_t2[2][100];   // head only (fp32)
    __shared__ __align__(16) float sh_part[32 * 2 * 100];
    __shared__ float sh_dt[NT];
    // dup-half2 state shadows for phase-1 HFMA2 (lane0 == lane1 == value)
    __shared__ __align__(8) __half2 shd_h [2][NH];
    __shared__ __align__(8) __half2 shd_hs[2][NH];
    __shared__ __align__(8) __half2 shd_ho[2][NH];
    __shared__ __align__(8) __half2 shd_ch[2][NH];
    __shared__ __align__(8) __half2 shd_cs[2][NH];
    // fp16 activation vectors for phase-2 HFMA2 ([row][j2] as half2)
    __shared__ __align__(8) __half2 sh16_t1[2][50];
    __shared__ __align__(8) __half2 sh16_t2[2][50];
    // smem-staged biases
    __shared__ float sb_bo1[100];
    __shared__ float sb_bo2[NH];
    __shared__ float sb_bu2[NH];
    __shared__ float sb_br2[NH];
    __shared__ float sb_bn2[2 * NH];

    const int tid = threadIdx.x;
    const int b0  = blockIdx.x * 2;
    const __half2 hz = __float2half2_rn(0.f);

    // phase-1 mappings
    const int g25 = tid % 25;           // j-group: cols 4g..4g+3
    const int c32 = tid / 25;           // chunk 0..31 (tid<800)
    const int gateB = tid / 400;        // B1: 0=u, 1=r
    const int sB    = tid % 400;
    const int cB    = sB / 25;          // 0..15
    const int gB    = sB % 25;
    // reduce mappings
    const int rrow  = (tid / 100) & 1, rj = tid % 100;
    const int rgate = tid / 200;
    // phase-2 column mappings
    const int gcol  = tid >> 9;          // row for A2; gate/half for B2/C2/head
    const int col   = tid & 511;

    // init: dt table, biases, zero states
    if (tid < NT) {
        float v;
        if (tid == 0)      v = -0.01f;
        else if (tid == 1) v = xt[NT - 1] - xt[0];
        else               v = xt[tid - 2] - xt[tid - 1];
        sh_dt[tid] = v;
    }
    if (tid < 100) sb_bo1[tid] = bo1[tid];
    if (tid < NH) {
        sb_bo2[tid] = bo2[tid];
        sb_bu2[tid] = bu2[tid];
        sb_br2[tid] = br2[tid];
    }
    sb_bn2[tid] = bn2[tid];
    for (int k = tid; k < NH; k += NTH) {
        sh_h[0][k] = 0.f; sh_h[1][k] = 0.f;
        sh_hs[0][k] = 0.f; sh_hs[1][k] = 0.f;
        shd_h[0][k] = hz; shd_h[1][k] = hz;
        shd_hs[0][k] = hz; shd_hs[1][k] = hz;
    }
    __syncthreads();

    for (int t = 0; t < NT; t++) {
        const float dt = sh_dt[t];

        // Prefetch this step's x-projection values.
        float pf_ur = 0.f, pf_n = 0.f;
        if (tid < 400) {
            int idx = (t * NB + b0 + rrow) * 100 + rj;
            pf_ur = rgate ? __ldg(g_xpr + idx) : __ldg(g_xpu + idx);
            if (tid < 200) pf_n = __ldg(g_xpn + idx);
        }

        // ---- Phase A1: a = tanh(h @ Wo1 + bo1); 32 chunks x 8 k2; HFMA2 ----
        if (tid < 800) {
            float4 a0 = {0.f,0.f,0.f,0.f}, a1 = {0.f,0.f,0.f,0.f};
            __half2 A00 = hz, A01 = hz, A10 = hz, A11 = hz;
            const __half* wp = g_hWo1 + ((size_t)(c32 * 8) * 25 + g25) * 8;
            const __half2* sp0 = &shd_h[0][c32 * 16];
            const __half2* sp1 = &shd_h[1][c32 * 16];
#pragma unroll
            for (int k2 = 0; k2 < 8; k2++) {
                P1H_STEP(wp, sp0[2*k2], sp0[2*k2+1], sp1[2*k2], sp1[2*k2+1],
                         A00, A01, A10, A11);
                wp += 200;
            }
            promote2(a0.x, a0.y, A00); promote2(a0.z, a0.w, A01);
            promote2(a1.x, a1.y, A10); promote2(a1.z, a1.w, A11);
            *reinterpret_cast<float4*>(&sh_part[(c32 * 2 + 0) * 100 + 4 * g25]) = a0;
            *reinterpret_cast<float4*>(&sh_part[(c32 * 2 + 1) * 100 + 4 * g25]) = a1;
        }
        __syncthreads();
        if (tid < 200) {
            float s = sb_bo1[rj];
#pragma unroll
            for (int cc = 0; cc < 32; cc++) s += sh_part[(cc * 2 + rrow) * 100 + rj];
            reinterpret_cast<__half*>(&sh16_t1[rrow][0])[rj] = __float2half_rn(fast_tanh(s));
        }
        __syncthreads();

        // ---- Phase A2: h_ode = h + dt*(a @ Wo2 + bo2); ALL 1024 threads ----
        {
            float f = sb_bo2[col];
            __half2 a = hz;
            const __half2* wp = reinterpret_cast<const __half2*>(g_hWo2) + col;
            const __half2* tp = &sh16_t1[gcol][0];
#pragma unroll
            for (int run = 0; run < 5; run++) {
#pragma unroll
                for (int jj = 0; jj < 10; jj++) {
                    a = __hfma2(tp[run * 10 + jj], *wp, a);
                    wp += NH;
                }
                promote(f, a);
            }
            float ho = sh_h[gcol][col] + dt * f;
            sh_ho[gcol][col] = ho;
            shd_ho[gcol][col] = __float2half2_rn(ho);
        }
        __syncthreads();

        // ---- Phase B1: tu/tr = tanh(xp + [ho,hs] @ W{u,r}1); 16 chunks x 32 k2; HFMA2 ----
        if (tid < 800) {
            float4 a0 = {0.f,0.f,0.f,0.f}, a1 = {0.f,0.f,0.f,0.f};
            const int kk0 = cB * 64;
            const __half* wp = (gateB ? g_hWr1 : g_hWu1) + ((size_t)(cB * 32) * 25 + gB) * 8;
            const __half2 *sp0, *sp1;
            if (cB < 8) { sp0 = &shd_ho[0][kk0];      sp1 = &shd_ho[1][kk0]; }
            else        { sp0 = &shd_hs[0][kk0 - NH]; sp1 = &shd_hs[1][kk0 - NH]; }
#pragma unroll
            for (int run = 0; run < 2; run++) {
                __half2 A00 = hz, A01 = hz, A10 = hz, A11 = hz;
#pragma unroll
                for (int kk = 0; kk < 16; kk++) {
                    int k2 = run * 16 + kk;
                    P1H_STEP(wp, sp0[2*k2], sp0[2*k2+1], sp1[2*k2], sp1[2*k2+1],
                             A00, A01, A10, A11);
                    wp += 200;
                }
                promote2(a0.x, a0.y, A00); promote2(a0.z, a0.w, A01);
                promote2(a1.x, a1.y, A10); promote2(a1.z, a1.w, A11);
            }
            *reinterpret_cast<float4*>(&sh_part[(cB * 4 + gateB * 2 + 0) * 100 + 4 * gB]) = a0;
            *reinterpret_cast<float4*>(&sh_part[(cB * 4 + gateB * 2 + 1) * 100 + 4 * gB]) = a1;
        }
        __syncthreads();
        if (tid < 400) {
            if (rgate == 0) {
                float su = pf_ur;
#pragma unroll
                for (int cc = 0; cc < 16; cc++) su += sh_part[(cc * 4 + rrow) * 100 + rj];
                reinterpret_cast<__half*>(&sh16_t1[rrow][0])[rj] = __float2half_rn(fast_tanh(su));
            } else {
                float sr = pf_ur;
#pragma unroll
                for (int cc = 0; cc < 16; cc++) sr += sh_part[(cc * 4 + 2 + rrow) * 100 + rj];
                reinterpret_cast<__half*>(&sh16_t2[rrow][0])[rj] = __float2half_rn(fast_tanh(sr));
            }
        }
        __syncthreads();

        // ---- Phase B2: u/r per column, both rows; HFMA2, gate-split halves ----
        if (gcol == 0) {
            float f0 = sb_bu2[col], f1 = f0;
            __half2 a0 = hz, a1 = hz;
            const __half2* wp = reinterpret_cast<const __half2*>(g_hWu2) + col;
#pragma unroll
            for (int run = 0; run < 5; run++) {
#pragma unroll
                for (int jj = 0; jj < 10; jj++) {
                    __half2 w = *wp; wp += NH;
                    a0 = __hfma2(sh16_t1[0][run * 10 + jj], w, a0);
                    a1 = __hfma2(sh16_t1[1][run * 10 + jj], w, a1);
                }
                promote(f0, a0); promote(f1, a1);
            }
            sh_u[0][col] = sigm(f0);
            sh_u[1][col] = sigm(f1);
        } else {
            float f0 = sb_br2[col], f1 = f0;
            __half2 a0 = hz, a1 = hz;
            const __half2* wp = reinterpret_cast<const __half2*>(g_hWr2) + col;
#pragma unroll
            for (int run = 0; run < 5; run++) {
#pragma unroll
                for (int jj = 0; jj < 10; jj++) {
                    __half2 w = *wp; wp += NH;
                    a0 = __hfma2(sh16_t2[0][run * 10 + jj], w, a0);
                    a1 = __hfma2(sh16_t2[1][run * 10 + jj], w, a1);
                }
                promote(f0, a0); promote(f1, a1);
            }
            float r0 = sigm(f0), r1 = sigm(f1);
            shd_ch[0][col] = __float2half2_rn(sh_ho[0][col] * r0);
            shd_ch[1][col] = __float2half2_rn(sh_ho[1][col] * r1);
            shd_cs[0][col] = __float2half2_rn(sh_hs[0][col] * r0);
            shd_cs[1][col] = __float2half2_rn(sh_hs[1][col] * r1);
        }
        __syncthreads();

        // ---- Phase C1: tn = tanh(xpn + [ch,cs] @ Wn1); 32 chunks x 16 k2; HFMA2 ----
        if (tid < 800) {
            float4 a0 = {0.f,0.f,0.f,0.f}, a1 = {0.f,0.f,0.f,0.f};
            __half2 A00 = hz, A01 = hz, A10 = hz, A11 = hz;
            const int kk0 = c32 * 32;
            const __half* wp = g_hWn1 + ((size_t)(c32 * 16) * 25 + g25) * 8;
            const __half2 *sp0, *sp1;
            if (kk0 < NH) { sp0 = &shd_ch[0][kk0];      sp1 = &shd_ch[1][kk0]; }
            else          { sp0 = &shd_cs[0][kk0 - NH]; sp1 = &shd_cs[1][kk0 - NH]; }
#pragma unroll
            for (int k2 = 0; k2 < 16; k2++) {
                P1H_STEP(wp, sp0[2*k2], sp0[2*k2+1], sp1[2*k2], sp1[2*k2+1],
                         A00, A01, A10, A11);
                wp += 200;
            }
            promote2(a0.x, a0.y, A00); promote2(a0.z, a0.w, A01);
            promote2(a1.x, a1.y, A10); promote2(a1.z, a1.w, A11);
            *reinterpret_cast<float4*>(&sh_part[(c32 * 2 + 0) * 100 + 4 * g25]) = a0;
            *reinterpret_cast<float4*>(&sh_part[(c32 * 2 + 1) * 100 + 4 * g25]) = a1;
        }
        __syncthreads();
        if (tid < 200) {
            float sn = pf_n;
#pragma unroll
            for (int cc = 0; cc < 32; cc++) sn += sh_part[(cc * 2 + rrow) * 100 + rj];
            reinterpret_cast<__half*>(&sh16_t1[rrow][0])[rj] = __float2half_rn(fast_tanh(sn));
        }
        __syncthreads();

        // ---- Phase C2: ns = tn @ Wn2 + bn2; m/s per column; HFMA2 ----
        {
            float f0 = sb_bn2[gcol * NH + col], f1 = f0;
            __half2 a0 = hz, a1 = hz;
            const __half2* wp = reinterpret_cast<const __half2*>(g_hWn2) + gcol * NH + col;
#pragma unroll
            for (int run = 0; run < 5; run++) {
#pragma unroll
                for (int jj = 0; jj < 10; jj++) {
                    __half2 w = *wp; wp += 2 * NH;
                    a0 = __hfma2(sh16_t1[0][run * 10 + jj], w, a0);
                    a1 = __hfma2(sh16_t1[1][run * 10 + jj], w, a1);
                }
                promote(f0, a0); promote(f1, a1);
            }
            float u0 = sh_u[0][col], u1 = sh_u[1][col];
            if (gcol == 0) {
                float h0 = (1.f - u0) * f0 + u0 * sh_ho[0][col];
                float h1 = (1.f - u1) * f1 + u1 * sh_ho[1][col];
                sh_h[0][col] = h0; sh_h[1][col] = h1;
                shd_h[0][col] = __float2half2_rn(h0);
                shd_h[1][col] = __float2half2_rn(h1);
            } else {
                float s0 = (1.f - u0) * fabsf(f0) + u0 * sh_hs[0][col];
                float s1 = (1.f - u1) * fabsf(f1) + u1 * sh_hs[1][col];
                sh_hs[0][col] = s0; sh_hs[1][col] = s1;
                shd_hs[0][col] = __float2half2_rn(s0);
                shd_hs[1][col] = __float2half2_rn(s1);
            }
        }
        __syncthreads();
    }

    // ================= Final head (fp32, run once) =================
    if (tid < 800) {
        float4 a0 = {0.f,0.f,0.f,0.f}, a1 = {0.f,0.f,0.f,0.f};
        const int kk0 = c32 * 32;
        const float* wp = Wt1 + kk0 * 100 + 4 * g25;
        const float *sp0, *sp1;
        if (kk0 < NH) { sp0 = &sh_h[0][kk0];       sp1 = &sh_h[1][kk0]; }
        else          { sp0 = &sh_hs[0][kk0 - NH]; sp1 = &sh_hs[1][kk0 - NH]; }
#pragma unroll 8
        for (int kc = 0; kc < 32; kc++) {
            float4 w = *reinterpret_cast<const float4*>(wp); wp += 100;
            float v0 = sp0[kc], v1 = sp1[kc];
            a0.x += v0 * w.x; a0.y += v0 * w.y; a0.z += v0 * w.z; a0.w += v0 * w.w;
            a1.x += v1 * w.x; a1.y += v1 * w.y; a1.z += v1 * w.z; a1.w += v1 * w.w;
        }
        *reinterpret_cast<float4*>(&sh_part[(c32 * 2 + 0) * 100 + 4 * g25]) = a0;
        *reinterpret_cast<float4*>(&sh_part[(c32 * 2 + 1) * 100 + 4 * g25]) = a1;
    }
    __syncthreads();
    if (tid < 200) {
        float s = bt1[rj];
#pragma unroll
        for (int cc = 0; cc < 32; cc++) s += sh_part[(cc * 2 + rrow) * 100 + rj];
        sh_t1[rrow][rj] = tanhf(s);
    }
    __syncthreads();
    if (tid < 200) {
        float s = bt2[rj];
#pragma unroll 4
        for (int jj = 0; jj < 100; jj++) s += sh_t1[rrow][jj] * Wt2[jj * 100 + rj];
        sh_t2[rrow][rj] = tanhf(s);
    }
    __syncthreads();
    {
        float b = bt3[tid];
        float a0 = b, a1 = b;
        const float* wp = Wt3 + tid;
#pragma unroll 10
        for (int j = 0; j < 100; j++) {
            float w = *wp; wp += 2 * NH;
            a0 += sh_t2[0][j] * w;
            a1 += sh_t2[1][j] * w;
        }
        if (gcol == 0) {
            out[(size_t)(b0 + 0) * NH + col] = a0;
            out[(size_t)(b0 + 1) * NH + col] = a1;
        } else {
            out[(size_t)NB * NH + (size_t)(b0 + 0) * NH + col] = fabsf(a0);
            out[(size_t)NB * NH + (size_t)(b0 + 1) * NH + col] = fabsf(a1);
        }
    }
}

// ---------------------------------------------------------------------------
extern "C" void kernel_launch(void* const* d_in, const int* in_sizes, int n_in,
                              void* d_out, int out_size) {
    const float* x   = (const float*)d_in[0];
    const float* xt  = (const float*)d_in[1];
    const float* Wu1 = (const float*)d_in[2];
    const float* bu1 = (const float*)d_in[3];
    const float* Wu2 = (const float*)d_in[4];
    const float* bu2 = (const float*)d_in[5];
    const float* Wr1 = (const float*)d_in[6];
    const float* br1 = (const float*)d_in[7];
    const float* Wr2 = (const float*)d_in[8];
    const float* br2 = (const float*)d_in[9];
    const float* Wn1 = (const float*)d_in[10];
    const float* bn1 = (const float*)d_in[11];
    const float* Wn2 = (const float*)d_in[12];
    const float* bn2 = (const float*)d_in[13];
    const float* Wo1 = (const float*)d_in[14];
    const float* bo1 = (const float*)d_in[15];
    const float* Wo2 = (const float*)d_in[16];
    const float* bo2 = (const float*)d_in[17];
    const float* Wt1 = (const float*)d_in[18];
    const float* bt1 = (const float*)d_in[19];
    const float* Wt2 = (const float*)d_in[20];
    const float* bt2 = (const float*)d_in[21];
    const float* Wt3 = (const float*)d_in[22];
    const float* bt3 = (const float*)d_in[23];
    float* out = (float*)d_out;

    __half *hWo1, *hWu1, *hWr1, *hWn1, *hWo2, *hWu2, *hWr2, *hWn2;
    cudaGetSymbolAddress((void**)&hWo1, g_hWo1);
    cudaGetSymbolAddress((void**)&hWu1, g_hWu1);
    cudaGetSymbolAddress((void**)&hWr1, g_hWr1);
    cudaGetSymbolAddress((void**)&hWn1, g_hWn1);
    cudaGetSymbolAddress((void**)&hWo2, g_hWo2);
    cudaGetSymbolAddress((void**)&hWu2, g_hWu2);
    cudaGetSymbolAddress((void**)&hWr2, g_hWr2);
    cudaGetSymbolAddress((void**)&hWn2, g_hWn2);

    pack_p1_kernel<<<200, 256>>>(Wo1, hWo1, 512);
    pack_p1_kernel<<<400, 256>>>(Wu1, hWu1, 1024);
    pack_p1_kernel<<<400, 256>>>(Wr1, hWr1, 1024);
    pack_p1_kernel<<<400, 256>>>(Wn1, hWn1, 1024);
    pack_p2_kernel<<<200, 256>>>(Wo2, hWo2, 512);
    pack_p2_kernel<<<200, 256>>>(Wu2, hWu2, 512);
    pack_p2_kernel<<<200, 256>>>(Wr2, hWr2, 512);
    pack_p2_kernel<<<400, 256>>>(Wn2, hWn2, 1024);

    dim3 pgrid(NT, 16);
    prep_xproj_kernel<<<pgrid, 256>>>(x, Wu1, bu1, Wr1, br1, Wn1, bn1);
    odegru_kernel<<<NB / 2, NTH>>>(xt,
        Wt1, bt1, Wt2, bt2, Wt3, bt3,
        bo1, bo2, bu2, br2, bn2, out);
}